// round 12
// baseline (speedup 1.0000x reference)
#include <cuda_runtime.h>
#include <math.h>

#define NPTS  14
#define NEDGE 13
#define NF1   3
#define BMAX  65536
#define FDIM  512
#define H1    64
#define H2    32
#define NSEG  (H1 + 1)
#define SROW4 9            // 9 float4 = 36 floats padded row
#define BIGF  1e30f
#define DIAGG 296          // diag grid
#define MSTB  513          // max mst blocks (BMAX/128 + 1)

// ---------------- scratch (all write-once per launch; no zero-init needed) --------
__device__ float  g_deaths0[NEDGE * BMAX];
__device__ float  g_dmax[BMAX];
__device__ float  g_p0[BMAX];
__device__ float  g_p1b[BMAX];
__device__ float  g_p1d[BMAX];
__device__ float  g_sp0[MSTB];          // per-mst-block entropy denom partials
__device__ float  g_sp1[MSTB];
__device__ float  g_h2p0[DIAGG * H2];   // per-diag-block h2 partials (diag0)
__device__ float  g_h2p1[DIAGG * H2];   // per-diag-block h2 partials (diag1)
__device__ float  g_epart[DIAGG];       // per-diag-block entropy partials
__device__ float  g_bp0[H1];
__device__ float  g_bp1[H1];
__device__ float4 g_A4[NSEG * SROW4];
__device__ float4 g_C4[NSEG * SROW4];
__device__ float4 g_P4[NSEG * SROW4];
__device__ float4 g_Q4[NSEG * SROW4];
__device__ int    g_fast;
__device__ int    g_done = 0;           // last-block counter (self-resetting)

__device__ __forceinline__ float warp_red(float v) {
#pragma unroll
    for (int o = 16; o; o >>= 1) v += __shfl_xor_sync(0xffffffffu, v, o);
    return v;
}

// 16-wide dot (fallback path)
__device__ __forceinline__ float dot16(float4 ha, float4 hb, float4 hc, float4 hd,
                                       const float* base) {
    const float4* wv = (const float4*)base;
    float4 w0 = wv[0], w1 = wv[1], w2 = wv[2], w3 = wv[3];
    float s;
    s = ha.x * w0.x;
    s = fmaf(ha.y, w0.y, s); s = fmaf(ha.z, w0.z, s); s = fmaf(ha.w, w0.w, s);
    s = fmaf(hb.x, w1.x, s); s = fmaf(hb.y, w1.y, s); s = fmaf(hb.z, w1.z, s); s = fmaf(hb.w, w1.w, s);
    s = fmaf(hc.x, w2.x, s); s = fmaf(hc.y, w2.y, s); s = fmaf(hc.z, w2.z, s); s = fmaf(hc.w, w2.w, s);
    s = fmaf(hd.x, w3.x, s); s = fmaf(hd.y, w3.y, s); s = fmaf(hd.z, w3.z, s); s = fmaf(hd.w, w3.w, s);
    return s;
}

// ---------------- k_mst: MST blocks + one table-builder block ----------------
__global__ void __launch_bounds__(128)
k_mst(const float* __restrict__ pc, const float* __restrict__ rb,
      const float* __restrict__ rd,
      const float* __restrict__ W1, const float* __restrict__ b1,
      const float* __restrict__ W2, const float* __restrict__ b2,
      float* __restrict__ euler, int B) {
    int nblkm = gridDim.x - 1;
    int tid = threadIdx.x;
    const float INF = __int_as_float(0x7f800000);

    if (blockIdx.x == (unsigned)nblkm) {
        // ======== table-builder block (runs concurrently with MST blocks) ========
        __shared__ float sb0[H1], sb1[H1], st[H1];
        __shared__ int s_nz;
        if (tid == 0) s_nz = 0;
        __syncthreads();
        if (tid < H1) {
            float w = W1[H1 + tid];
            st[tid] = (w != 0.f) ? (-b1[tid] / w) : INF;
            if (b1[tid] != 0.f) atomicAdd(&s_nz, 1);
        }
        __syncthreads();
        if (tid < H1) {
            float t = st[tid];
            int r = 0;
#pragma unroll
            for (int i = 0; i < H1; i++) {
                float ti = st[i];
                r += (ti < t || (ti == t && i < tid)) ? 1 : 0;
            }
            sb0[r] = t; g_bp0[r] = t;
        }
        __syncthreads();
        if (tid < H1) {
            float w0 = W1[tid], w1 = W1[H1 + tid];
            st[tid] = (w0 != 0.f) ? (-w1 / w0) : INF;
        }
        __syncthreads();
        if (tid < H1) {
            float t = st[tid];
            int r = 0;
#pragma unroll
            for (int i = 0; i < H1; i++) {
                float ti = st[i];
                r += (ti < t || (ti == t && i < tid)) ? 1 : 0;
            }
            sb1[r] = t; g_bp1[r] = t;
        }
        if (tid == 0) g_fast = (s_nz == 0) ? 1 : 0;
        __syncthreads();
        for (int e = tid; e < NSEG * H2; e += blockDim.x) {
            int s = e >> 5, k = e & 31;
            {   // diag0 tables (segment in d)
                float lo = (s == 0)  ? -INF : sb0[s - 1];
                float hi = (s == H1) ?  INF : sb0[s];
                float rep;
                bool li = isinf(lo), hiinf = isinf(hi);
                if (li && hiinf)      rep = 0.f;
                else if (li)          rep = hi - 1.f;
                else if (hiinf)       rep = lo + 1.f;
                else                  rep = 0.5f * (lo + hi);
                float A = 0.f, C = b2[k];
                for (int j = 0; j < H1; j++) {
                    float w = W1[H1 + j], bb = b1[j];
                    bool act = (w == 0.f) ? (bb > 0.f) : ((w * rep + bb) > 0.f);
                    if (act) {
                        float m = W2[j * H2 + k];
                        A += w * m;
                        C += bb * m;
                    }
                }
                ((float*)g_A4)[s * (SROW4 * 4) + k] = A;
                ((float*)g_C4)[s * (SROW4 * 4) + k] = C;
            }
            {   // diag1 tables (segment in t = x/y)
                float lo = (s == 0)  ? -INF : sb1[s - 1];
                float hi = (s == H1) ?  INF : sb1[s];
                float rep;
                bool li = isinf(lo), hiinf = isinf(hi);
                if (li && hiinf)      rep = 0.f;
                else if (li)          rep = hi - 1.f;
                else if (hiinf)       rep = lo + 1.f;
                else                  rep = 0.5f * (lo + hi);
                float P = 0.f, Q = 0.f;
                for (int j = 0; j < H1; j++) {
                    float w0 = W1[j], w1 = W1[H1 + j];
                    bool act = (w0 == 0.f) ? (w1 > 0.f) : ((w0 * rep + w1) > 0.f);
                    if (act) {
                        float m = W2[j * H2 + k];
                        P += w0 * m;
                        Q += w1 * m;
                    }
                }
                ((float*)g_P4)[s * (SROW4 * 4) + k] = P;
                ((float*)g_Q4)[s * (SROW4 * 4) + k] = Q;
            }
        }
        return;
    }

    // ======== MST blocks ========
    __shared__ float spc[128 * NPTS * 3];
    {
        long long base = (long long)blockIdx.x * 128 * (NPTS * 3);
        int nrow = B - blockIdx.x * 128;
        if (nrow >= 128) {
            const float4* src = (const float4*)(pc + base);
#pragma unroll 1
            for (int i = tid; i < 128 * NPTS * 3 / 4; i += 128)
                ((float4*)spc)[i] = src[i];
        } else if (nrow > 0) {
            int n = nrow * NPTS * 3;
            for (int i = tid; i < n; i += 128) spc[i] = pc[base + i];
        }
    }
    __syncthreads();

    int b = blockIdx.x * blockDim.x + tid;
    float s0 = 0.f, s1 = 0.f;
    if (b < B) {
        const float* p = spc + tid * (NPTS * 3);
        float px[NPTS], py[NPTS], pz[NPTS];
#pragma unroll
        for (int i = 0; i < NPTS; i++) {
            px[i] = p[3 * i]; py[i] = p[3 * i + 1]; pz[i] = p[3 * i + 2];
        }
        float key[NPTS];
        float dmax2 = 0.f;
        key[0] = BIGF;
#pragma unroll
        for (int i = 1; i < NPTS; i++) {
            float dx = px[i] - px[0], dy = py[i] - py[0], dz = pz[i] - pz[0];
            float d2 = dx * dx + dy * dy + dz * dz;
            key[i] = d2;
            dmax2 = fmaxf(dmax2, d2);
        }
        float m1 = BIGF, m2 = BIGF;
#pragma unroll 1
        for (int it = 0; it < NEDGE; it++) {
#define MINP(AV, AI, BV, BI, OV, OI) \
            { bool c = (BV) < (AV); OV = c ? (BV) : (AV); OI = c ? (BI) : (AI); }
            float v12, v34, v56, v78, v910, v1112;
            int   i12, i34, i56, i78, i910, i1112;
            MINP(key[1], 1, key[2], 2, v12, i12)
            MINP(key[3], 3, key[4], 4, v34, i34)
            MINP(key[5], 5, key[6], 6, v56, i56)
            MINP(key[7], 7, key[8], 8, v78, i78)
            MINP(key[9], 9, key[10], 10, v910, i910)
            MINP(key[11], 11, key[12], 12, v1112, i1112)
            float va, vb, vc; int ia, ib, ic;
            MINP(v12, i12, v34, i34, va, ia)
            MINP(v56, i56, v78, i78, vb, ib)
            MINP(v910, i910, v1112, i1112, vc, ic)
            float vab; int iab;
            MINP(va, ia, vb, ib, vab, iab)
            float vcd; int icd;
            MINP(vc, ic, key[13], 13, vcd, icd)
            float bv; int bj;
            MINP(vab, iab, vcd, icd, bv, bj)
#undef MINP
            if (bv < m1) { m2 = m1; m1 = bv; } else if (bv < m2) { m2 = bv; }
            g_deaths0[it * B + b] = sqrtf(fmaxf(bv, 1e-24f));
            float qx = px[0], qy = py[0], qz = pz[0];
#pragma unroll
            for (int c = 1; c < NPTS; c++) {
                if (bj == c) { qx = px[c]; qy = py[c]; qz = pz[c]; }
            }
#pragma unroll
            for (int i = 1; i < NPTS; i++) {
                float dx = px[i] - qx, dy = py[i] - qy, dz = pz[i] - qz;
                float d2 = dx * dx + dy * dy + dz * dz;
                dmax2 = fmaxf(dmax2, d2);
                float nk = fminf(key[i], d2);
                key[i] = (i == bj || key[i] >= BIGF) ? BIGF : nk;
            }
        }
        float dmax = sqrtf(fmaxf(dmax2, 1e-24f));
        g_dmax[b] = dmax;
        float d0 = sqrtf(fmaxf(m1, 1e-24f));
        float d1 = sqrtf(fmaxf(m2, 1e-24f));
        float p0 = d1 - d0;
        g_p0[b] = p0;
        if (p0 > 0.f) s0 = p0;
        float p1b = (rb[b * NF1 + 1] - rb[b * NF1 + 0]) * dmax * 0.3f;
        float p1d = p1b + (rd[b * NF1 + 1] - rd[b * NF1 + 0]) * dmax * 0.4f;
        g_p1b[b] = p1b;
        g_p1d[b] = p1d;
        if (p1b > 0.f) s1 += p1b;
        if (p1d > 0.f) s1 += p1d;
        euler[b] = (float)(NEDGE - NF1);
    }
    __shared__ float s_e[2][4];
    int lane = tid & 31, wid = tid >> 5;
    int nw = blockDim.x >> 5;
    s0 = warp_red(s0);
    s1 = warp_red(s1);
    if (lane == 0) { s_e[0][wid] = s0; s_e[1][wid] = s1; }
    __syncthreads();
    if (wid == 0 && lane < 2) {
        float v = 0.f;
        for (int w = 0; w < nw; w++) v += s_e[lane][w];
        if (lane == 0) g_sp0[blockIdx.x] = v; else g_sp1[blockIdx.x] = v;
    }
}

// ---------------- k_diag: diag0 + diag1 + entropy + (last block) features --------
__global__ void __launch_bounds__(256)
k_diag(const float* __restrict__ W1, const float* __restrict__ b1,
       const float* __restrict__ W2, const float* __restrict__ b2,
       const float* __restrict__ rb, const float* __restrict__ rd,
       const float* __restrict__ W3, const float* __restrict__ b3,
       float* __restrict__ out, float* __restrict__ ent, int B, int nblkm) {
    __shared__ float  sbp0[H1], sbp1[H1];
    __shared__ __align__(16) float4 sA[NSEG * SROW4];
    __shared__ __align__(16) float4 sC[NSEG * SROW4];
    __shared__ __align__(16) float4 sP[NSEG * SROW4];
    __shared__ __align__(16) float4 sQ[NSEG * SROW4];
    __shared__ __align__(16) float4 sb2v[8];
    __shared__ float s_part[8][H2];
    __shared__ float s_bc[2][8];
    __shared__ int s_last;
    // fallback-only weights
    __shared__ __align__(16) float sw[H1 * 4];
    __shared__ __align__(16) float sW2t[H2 * H1];
    int tid = threadIdx.x;
    int fast = g_fast;
    for (int i = tid; i < H1; i += blockDim.x) { sbp0[i] = g_bp0[i]; sbp1[i] = g_bp1[i]; }
    for (int i = tid; i < NSEG * SROW4; i += blockDim.x) {
        sA[i] = g_A4[i]; sC[i] = g_C4[i];
        sP[i] = g_P4[i]; sQ[i] = g_Q4[i];
    }
    if (tid < 8) sb2v[tid] = ((const float4*)b2)[tid];
    if (!fast) {
        for (int j = tid; j < H1; j += blockDim.x) {
            sw[j * 4 + 0] = W1[j];
            sw[j * 4 + 1] = W1[H1 + j];
            sw[j * 4 + 2] = b1[j];
            sw[j * 4 + 3] = 0.f;
        }
        for (int i = tid; i < H1 * H2; i += blockDim.x) {
            int j = i / H2, k = i % H2;
            sW2t[k * H1 + j] = W2[i];
        }
    }
    __syncthreads();

    int lane = tid & 31, wid = tid >> 5;
    int nw = blockDim.x >> 5;
    int stride = gridDim.x * blockDim.x;
    int gbase = blockIdx.x * blockDim.x + tid;
    float4 z = make_float4(0.f, 0.f, 0.f, 0.f);

    // ================= phase A: diag0 over MST deaths =================
    {
        float4 a0 = z, a1 = z, a2 = z, a3 = z, a4 = z, a5 = z, a6 = z, a7 = z;
        int total = NEDGE * B;
        if (fast) {
            int lo = 0, hi = H1;
#pragma unroll
            for (int s = 0; s < 6; s++) {
                int mid = (lo + hi) >> 1;
                if (sbp0[mid] < 1e-20f) lo = mid + 1; else hi = mid;
            }
            const float4* Av = sA + lo * SROW4;
            const float4* Cv = sC + lo * SROW4;
            float4 A0 = Av[0], A1 = Av[1], A2 = Av[2], A3 = Av[3];
            float4 A4 = Av[4], A5 = Av[5], A6 = Av[6], A7 = Av[7];
            float4 C0 = Cv[0], C1 = Cv[1], C2 = Cv[2], C3 = Cv[3];
            float4 C4 = Cv[4], C5 = Cv[5], C6 = Cv[6], C7 = Cv[7];
            for (int i = gbase; i < total; i += stride) {
                float d = g_deaths0[i];
#define Q0(ACC, AV, CV) {                                                 \
                ACC.x += fmaxf(fmaf(AV.x, d, CV.x), 0.f);                 \
                ACC.y += fmaxf(fmaf(AV.y, d, CV.y), 0.f);                 \
                ACC.z += fmaxf(fmaf(AV.z, d, CV.z), 0.f);                 \
                ACC.w += fmaxf(fmaf(AV.w, d, CV.w), 0.f); }
                Q0(a0, A0, C0) Q0(a1, A1, C1) Q0(a2, A2, C2) Q0(a3, A3, C3)
                Q0(a4, A4, C4) Q0(a5, A5, C5) Q0(a6, A6, C6) Q0(a7, A7, C7)
#undef Q0
            }
        } else {
            for (int i = gbase; i < total; i += stride) {
                float d = g_deaths0[i];
                int lo = 0, hi = H1;
#pragma unroll
                for (int s = 0; s < 6; s++) {
                    int mid = (lo + hi) >> 1;
                    if (sbp0[mid] < d) lo = mid + 1; else hi = mid;
                }
                const float4* Av = sA + lo * SROW4;
                const float4* Cv = sC + lo * SROW4;
#define Q1(ACC, q) { float4 A = Av[q], C = Cv[q];                         \
                ACC.x += fmaxf(fmaf(A.x, d, C.x), 0.f);                   \
                ACC.y += fmaxf(fmaf(A.y, d, C.y), 0.f);                   \
                ACC.z += fmaxf(fmaf(A.z, d, C.z), 0.f);                   \
                ACC.w += fmaxf(fmaf(A.w, d, C.w), 0.f); }
                Q1(a0, 0) Q1(a1, 1) Q1(a2, 2) Q1(a3, 3)
                Q1(a4, 4) Q1(a5, 5) Q1(a6, 6) Q1(a7, 7)
#undef Q1
            }
        }
#define R(ACC, q) {                                                        \
        float vx = warp_red(ACC.x), vy = warp_red(ACC.y);                  \
        float vz = warp_red(ACC.z), vw = warp_red(ACC.w);                  \
        if (lane == 0) { s_part[wid][q * 4 + 0] = vx; s_part[wid][q * 4 + 1] = vy; \
                         s_part[wid][q * 4 + 2] = vz; s_part[wid][q * 4 + 3] = vw; } }
        R(a0, 0) R(a1, 1) R(a2, 2) R(a3, 3) R(a4, 4) R(a5, 5) R(a6, 6) R(a7, 7)
        __syncthreads();
        if (tid < H2) {
            float v = 0.f;
            for (int w = 0; w < nw; w++) v += s_part[w][tid];
            g_h2p0[blockIdx.x * H2 + tid] = v;
        }
        __syncthreads();
    }

    // ================= phase B: diag1 over random features =================
    {
        float4 c0 = z, c1 = z, c2 = z, c3 = z, c4 = z, c5 = z, c6 = z, c7 = z;
        int total = NF1 * B;
        if (fast) {
            float4 B0 = sb2v[0], B1 = sb2v[1], B2 = sb2v[2], B3 = sb2v[3];
            float4 B4 = sb2v[4], B5 = sb2v[5], B6 = sb2v[6], B7 = sb2v[7];
            for (int i = gbase; i < total; i += stride) {
                float dm = g_dmax[i / NF1];
                float x = rb[i] * dm * 0.3f;
                float y = fmaf(rd[i] * dm, 0.4f, x);
                float t = (y > 0.f) ? (x / y) : 0.f;
                int lo = 0, hi = H1;
#pragma unroll
                for (int s = 0; s < 6; s++) {
                    int mid = (lo + hi) >> 1;
                    if (sbp1[mid] < t) lo = mid + 1; else hi = mid;
                }
                const float4* Pv = sP + lo * SROW4;
                const float4* Qv = sQ + lo * SROW4;
#define Q2(ACC, q, BV) { float4 P = Pv[q], Q = Qv[q];                      \
                ACC.x += fmaxf(fmaf(y, fmaf(P.x, t, Q.x), BV.x), 0.f);     \
                ACC.y += fmaxf(fmaf(y, fmaf(P.y, t, Q.y), BV.y), 0.f);     \
                ACC.z += fmaxf(fmaf(y, fmaf(P.z, t, Q.z), BV.z), 0.f);     \
                ACC.w += fmaxf(fmaf(y, fmaf(P.w, t, Q.w), BV.w), 0.f); }
                Q2(c0, 0, B0) Q2(c1, 1, B1) Q2(c2, 2, B2) Q2(c3, 3, B3)
                Q2(c4, 4, B4) Q2(c5, 5, B5) Q2(c6, 6, B6) Q2(c7, 7, B7)
#undef Q2
            }
        } else {
            for (int i = gbase; i < total; i += stride) {
                float dm = g_dmax[i / NF1];
                float x = rb[i] * dm * 0.3f;
                float y = fmaf(rd[i] * dm, 0.4f, x);
                float4 t0 = sb2v[0], t1 = sb2v[1], t2 = sb2v[2], t3 = sb2v[3];
                float4 t4 = sb2v[4], t5 = sb2v[5], t6 = sb2v[6], t7 = sb2v[7];
#pragma unroll 1
                for (int jc = 0; jc < 4; jc++) {
                    const float4* swv = (const float4*)sw + jc * 16;
                    float4 ha, hb, hc, hd;
#define HV(DST, COMP, IDX) { float4 w = swv[IDX];                              \
                    DST.COMP = fmaxf(fmaf(x, w.x, fmaf(y, w.y, w.z)), 0.f); }
                    HV(ha, x, 0)  HV(ha, y, 1)  HV(ha, z, 2)  HV(ha, w, 3)
                    HV(hb, x, 4)  HV(hb, y, 5)  HV(hb, z, 6)  HV(hb, w, 7)
                    HV(hc, x, 8)  HV(hc, y, 9)  HV(hc, z, 10) HV(hc, w, 11)
                    HV(hd, x, 12) HV(hd, y, 13) HV(hd, z, 14) HV(hd, w, 15)
#undef HV
                    const float* wb = sW2t + jc * 16;
                    t0.x += dot16(ha, hb, hc, hd, wb + 0 * H1);
                    t0.y += dot16(ha, hb, hc, hd, wb + 1 * H1);
                    t0.z += dot16(ha, hb, hc, hd, wb + 2 * H1);
                    t0.w += dot16(ha, hb, hc, hd, wb + 3 * H1);
                    t1.x += dot16(ha, hb, hc, hd, wb + 4 * H1);
                    t1.y += dot16(ha, hb, hc, hd, wb + 5 * H1);
                    t1.z += dot16(ha, hb, hc, hd, wb + 6 * H1);
                    t1.w += dot16(ha, hb, hc, hd, wb + 7 * H1);
                    t2.x += dot16(ha, hb, hc, hd, wb + 8 * H1);
                    t2.y += dot16(ha, hb, hc, hd, wb + 9 * H1);
                    t2.z += dot16(ha, hb, hc, hd, wb + 10 * H1);
                    t2.w += dot16(ha, hb, hc, hd, wb + 11 * H1);
                    t3.x += dot16(ha, hb, hc, hd, wb + 12 * H1);
                    t3.y += dot16(ha, hb, hc, hd, wb + 13 * H1);
                    t3.z += dot16(ha, hb, hc, hd, wb + 14 * H1);
                    t3.w += dot16(ha, hb, hc, hd, wb + 15 * H1);
                    t4.x += dot16(ha, hb, hc, hd, wb + 16 * H1);
                    t4.y += dot16(ha, hb, hc, hd, wb + 17 * H1);
                    t4.z += dot16(ha, hb, hc, hd, wb + 18 * H1);
                    t4.w += dot16(ha, hb, hc, hd, wb + 19 * H1);
                    t5.x += dot16(ha, hb, hc, hd, wb + 20 * H1);
                    t5.y += dot16(ha, hb, hc, hd, wb + 21 * H1);
                    t5.z += dot16(ha, hb, hc, hd, wb + 22 * H1);
                    t5.w += dot16(ha, hb, hc, hd, wb + 23 * H1);
                    t6.x += dot16(ha, hb, hc, hd, wb + 24 * H1);
                    t6.y += dot16(ha, hb, hc, hd, wb + 25 * H1);
                    t6.z += dot16(ha, hb, hc, hd, wb + 26 * H1);
                    t6.w += dot16(ha, hb, hc, hd, wb + 27 * H1);
                    t7.x += dot16(ha, hb, hc, hd, wb + 28 * H1);
                    t7.y += dot16(ha, hb, hc, hd, wb + 29 * H1);
                    t7.z += dot16(ha, hb, hc, hd, wb + 30 * H1);
                    t7.w += dot16(ha, hb, hc, hd, wb + 31 * H1);
                }
#define EP(TP, ACC) { ACC.x += fmaxf(TP.x, 0.f); ACC.y += fmaxf(TP.y, 0.f);    \
                      ACC.z += fmaxf(TP.z, 0.f); ACC.w += fmaxf(TP.w, 0.f); }
                EP(t0, c0) EP(t1, c1) EP(t2, c2) EP(t3, c3)
                EP(t4, c4) EP(t5, c5) EP(t6, c6) EP(t7, c7)
#undef EP
            }
        }
        R(c0, 0) R(c1, 1) R(c2, 2) R(c3, 3) R(c4, 4) R(c5, 5) R(c6, 6) R(c7, 7)
#undef R
        __syncthreads();
        if (tid < H2) {
            float v = 0.f;
            for (int w = 0; w < nw; w++) v += s_part[w][tid];
            g_h2p1[blockIdx.x * H2 + tid] = v;
        }
        __syncthreads();
    }

    // ================= phase C: entropy (needs mst partials) =================
    {
        float s0 = 0.f, s1 = 0.f;
        for (int i = tid; i < nblkm; i += blockDim.x) { s0 += g_sp0[i]; s1 += g_sp1[i]; }
        s0 = warp_red(s0); s1 = warp_red(s1);
        if (lane == 0) { s_bc[0][wid] = s0; s_bc[1][wid] = s1; }
        __syncthreads();
        float S0 = 0.f, S1 = 0.f;
        for (int w = 0; w < nw; w++) { S0 += s_bc[0][w]; S1 += s_bc[1][w]; }
        S0 = fmaxf(S0, 1e-30f); S1 = fmaxf(S1, 1e-30f);
        float e = 0.f;
        for (int bb = gbase; bb < B; bb += stride) {
            float p = g_p0[bb];
            if (p > 0.f)  { float q = p  / S0; e -= q * logf(q + 1e-10f); }
            float pb = g_p1b[bb];
            if (pb > 0.f) { float q = pb / S1; e -= q * logf(q + 1e-10f); }
            float pd = g_p1d[bb];
            if (pd > 0.f) { float q = pd / S1; e -= q * logf(q + 1e-10f); }
        }
        e = warp_red(e);
        if (lane == 0) s_part[wid][0] = e;
        __syncthreads();
        if (tid == 0) {
            float v = 0.f;
            for (int w = 0; w < nw; w++) v += s_part[w][0];
            g_epart[blockIdx.x] = v;
        }
    }

    // ================= last block: features + entropy write =================
    __threadfence();
    if (tid == 0) s_last = (atomicAdd(&g_done, 1) == (int)gridDim.x - 1) ? 1 : 0;
    __syncthreads();
    if (s_last) {
        __shared__ float u[H2];
        if (tid < H2) {
            float v0 = 0.f, v1 = 0.f;
            for (int blk = 0; blk < DIAGG; blk++) {
                v0 += g_h2p0[blk * H2 + tid];
                v1 += g_h2p1[blk * H2 + tid];
            }
            u[tid] = v0 / ((float)NEDGE * (float)B) + v1 / ((float)NF1 * (float)B);
        }
        __syncthreads();
        for (int f = tid; f < FDIM; f += blockDim.x) {
            float t = 2.f * b3[f];
#pragma unroll
            for (int k = 0; k < H2; k++) t += u[k] * W3[k * FDIM + f];
            out[f] = t;
        }
        {
            float v = 0.f;
            for (int i = tid; i < DIAGG; i += blockDim.x) v += g_epart[i];
            v = warp_red(v);
            if (lane == 0) s_part[wid][1] = v;
            __syncthreads();
            if (tid == 0) {
                float tot = 0.f;
                for (int w = 0; w < nw; w++) tot += s_part[w][1];
                *ent = tot;
                g_done = 0;   // reset for next graph replay
            }
        }
    }
}

// ---------------- launch ----------------
extern "C" void kernel_launch(void* const* d_in, const int* in_sizes, int n_in,
                              void* d_out, int out_size) {
    const float* pc = (const float*)d_in[0];
    const float* rb = (const float*)d_in[1];
    const float* rd = (const float*)d_in[2];
    const float* W1 = (const float*)d_in[3];
    const float* b1 = (const float*)d_in[4];
    const float* W2 = (const float*)d_in[5];
    const float* b2 = (const float*)d_in[6];
    const float* W3 = (const float*)d_in[7];
    const float* b3 = (const float*)d_in[8];
    float* out = (float*)d_out;

    int B = in_sizes[1] / NF1;
    if (B > BMAX) B = BMAX;
    int nblkm = (B + 127) / 128;

    float* euler = out + FDIM;
    float* ent   = out + FDIM + B;

    k_mst<<<nblkm + 1, 128>>>(pc, rb, rd, W1, b1, W2, b2, euler, B);
    k_diag<<<DIAGG, 256>>>(W1, b1, W2, b2, rb, rd, W3, b3, out, ent, B, nblkm);
}

// round 15
// speedup vs baseline: 1.1455x; 1.1455x over previous
#include <cuda_runtime.h>
#include <math.h>

#define NPTS  14
#define NEDGE 13
#define NF1   3
#define BMAX  65536
#define FDIM  512
#define H1    64
#define H2    32
#define NSEG  (H1 + 1)
#define SROW4 9            // 9 float4 = 36 floats padded row
#define BIGF  1e30f
#define DIAGG 296          // diag grid
#define MSTB  520          // max mst blocks
#define NTBLK 4            // table-builder blocks

// ---------------- scratch (all write-once per launch; no zero-init needed) --------
__device__ float  g_deaths0[NEDGE * BMAX];
__device__ float  g_dmax[BMAX];
__device__ float  g_p0[BMAX];
__device__ float  g_p1b[BMAX];
__device__ float  g_p1d[BMAX];
__device__ float  g_sp0[MSTB];
__device__ float  g_sp1[MSTB];
__device__ float  g_h2p0[DIAGG * H2];
__device__ float  g_h2p1[DIAGG * H2];
__device__ float  g_epart[DIAGG];
__device__ float  g_bp0[H1];
__device__ float  g_bp1[H1];
__device__ float4 g_A4[NSEG * SROW4];
__device__ float4 g_C4[NSEG * SROW4];
__device__ float4 g_P4[NSEG * SROW4];
__device__ float4 g_Q4[NSEG * SROW4];
__device__ int    g_fast;
__device__ int    g_done = 0;

__device__ __forceinline__ float warp_red(float v) {
#pragma unroll
    for (int o = 16; o; o >>= 1) v += __shfl_xor_sync(0xffffffffu, v, o);
    return v;
}

// 16-wide dot (fallback path)
__device__ __forceinline__ float dot16(float4 ha, float4 hb, float4 hc, float4 hd,
                                       const float* base) {
    const float4* wv = (const float4*)base;
    float4 w0 = wv[0], w1 = wv[1], w2 = wv[2], w3 = wv[3];
    float s;
    s = ha.x * w0.x;
    s = fmaf(ha.y, w0.y, s); s = fmaf(ha.z, w0.z, s); s = fmaf(ha.w, w0.w, s);
    s = fmaf(hb.x, w1.x, s); s = fmaf(hb.y, w1.y, s); s = fmaf(hb.z, w1.z, s); s = fmaf(hb.w, w1.w, s);
    s = fmaf(hc.x, w2.x, s); s = fmaf(hc.y, w2.y, s); s = fmaf(hc.z, w2.z, s); s = fmaf(hc.w, w2.w, s);
    s = fmaf(hd.x, w3.x, s); s = fmaf(hd.y, w3.y, s); s = fmaf(hd.z, w3.z, s); s = fmaf(hd.w, w3.w, s);
    return s;
}

// ---------------- k_mst: MST blocks + NTBLK table-builder blocks ----------------
__global__ void __launch_bounds__(128)
k_mst(const float* __restrict__ pc, const float* __restrict__ rb,
      const float* __restrict__ rd,
      const float* __restrict__ W1, const float* __restrict__ b1,
      const float* __restrict__ W2, const float* __restrict__ b2,
      float* __restrict__ euler, int B) {
    int nblkm = gridDim.x - NTBLK;
    int tid = threadIdx.x;
    const float INF = __int_as_float(0x7f800000);

    if ((int)blockIdx.x >= nblkm) {
        // ======== table-builder blocks: weights staged in shared ========
        int rel = blockIdx.x - nblkm;            // 0..NTBLK-1
        __shared__ float sW1[2 * H1], sb1s[H1], sW2s[H1 * H2], sb2s[H2];
        __shared__ float sb0[H1], sb1b[H1], st[H1];
        __shared__ int s_nz;
        if (tid == 0) s_nz = 0;
        for (int i = tid; i < 2 * H1; i += blockDim.x) sW1[i] = W1[i];
        for (int i = tid; i < H1; i += blockDim.x) sb1s[i] = b1[i];
        for (int i = tid; i < H1 * H2; i += blockDim.x) sW2s[i] = W2[i];
        for (int i = tid; i < H2; i += blockDim.x) sb2s[i] = b2[i];
        __syncthreads();
        if (tid < H1) {
            float w = sW1[H1 + tid];
            st[tid] = (w != 0.f) ? (-sb1s[tid] / w) : INF;
            if (sb1s[tid] != 0.f) atomicAdd(&s_nz, 1);
        }
        __syncthreads();
        if (tid < H1) {
            float t = st[tid];
            int r = 0;
#pragma unroll
            for (int i = 0; i < H1; i++) {
                float ti = st[i];
                r += (ti < t || (ti == t && i < tid)) ? 1 : 0;
            }
            sb0[r] = t;
            if (rel == 0) g_bp0[r] = t;
        }
        __syncthreads();
        if (tid < H1) {
            float w0 = sW1[tid], w1 = sW1[H1 + tid];
            st[tid] = (w0 != 0.f) ? (-w1 / w0) : INF;
        }
        __syncthreads();
        if (tid < H1) {
            float t = st[tid];
            int r = 0;
#pragma unroll
            for (int i = 0; i < H1; i++) {
                float ti = st[i];
                r += (ti < t || (ti == t && i < tid)) ? 1 : 0;
            }
            sb1b[r] = t;
            if (rel == 0) g_bp1[r] = t;
        }
        if (rel == 0 && tid == 0) g_fast = (s_nz == 0) ? 1 : 0;
        __syncthreads();
        int gt = rel * 128 + tid;                // 0..511
        for (int e = gt; e < NSEG * H2; e += NTBLK * 128) {
            int s = e >> 5, k = e & 31;
            {   // diag0 tables (segment in d)
                float lo = (s == 0)  ? -INF : sb0[s - 1];
                float hi = (s == H1) ?  INF : sb0[s];
                float rep;
                bool li = isinf(lo), hiinf = isinf(hi);
                if (li && hiinf)      rep = 0.f;
                else if (li)          rep = hi - 1.f;
                else if (hiinf)       rep = lo + 1.f;
                else                  rep = 0.5f * (lo + hi);
                float A = 0.f, C = sb2s[k];
#pragma unroll 1
                for (int j = 0; j < H1; j++) {
                    float w = sW1[H1 + j], bb = sb1s[j];
                    bool act = (w == 0.f) ? (bb > 0.f) : ((w * rep + bb) > 0.f);
                    if (act) {
                        float m = sW2s[j * H2 + k];
                        A += w * m;
                        C += bb * m;
                    }
                }
                ((float*)g_A4)[s * (SROW4 * 4) + k] = A;
                ((float*)g_C4)[s * (SROW4 * 4) + k] = C;
            }
            {   // diag1 tables (segment in t = x/y)
                float lo = (s == 0)  ? -INF : sb1b[s - 1];
                float hi = (s == H1) ?  INF : sb1b[s];
                float rep;
                bool li = isinf(lo), hiinf = isinf(hi);
                if (li && hiinf)      rep = 0.f;
                else if (li)          rep = hi - 1.f;
                else if (hiinf)       rep = lo + 1.f;
                else                  rep = 0.5f * (lo + hi);
                float P = 0.f, Q = 0.f;
#pragma unroll 1
                for (int j = 0; j < H1; j++) {
                    float w0 = sW1[j], w1 = sW1[H1 + j];
                    bool act = (w0 == 0.f) ? (w1 > 0.f) : ((w0 * rep + w1) > 0.f);
                    if (act) {
                        float m = sW2s[j * H2 + k];
                        P += w0 * m;
                        Q += w1 * m;
                    }
                }
                ((float*)g_P4)[s * (SROW4 * 4) + k] = P;
                ((float*)g_Q4)[s * (SROW4 * 4) + k] = Q;
            }
        }
        return;
    }

    // ======== MST blocks ========
    __shared__ float spc[128 * NPTS * 3];
    {
        long long base = (long long)blockIdx.x * 128 * (NPTS * 3);
        int nrow = B - blockIdx.x * 128;
        if (nrow >= 128) {
            const float4* src = (const float4*)(pc + base);
#pragma unroll 1
            for (int i = tid; i < 128 * NPTS * 3 / 4; i += 128)
                ((float4*)spc)[i] = src[i];
        } else if (nrow > 0) {
            int n = nrow * NPTS * 3;
            for (int i = tid; i < n; i += 128) spc[i] = pc[base + i];
        }
    }
    __syncthreads();

    int b = blockIdx.x * blockDim.x + tid;
    float s0 = 0.f, s1 = 0.f;
    if (b < B) {
        const float* p = spc + tid * (NPTS * 3);
        float px[NPTS], py[NPTS], pz[NPTS];
#pragma unroll
        for (int i = 0; i < NPTS; i++) {
            px[i] = p[3 * i]; py[i] = p[3 * i + 1]; pz[i] = p[3 * i + 2];
        }
        float key[NPTS];
        float dmax2 = 0.f;
        key[0] = BIGF;
#pragma unroll
        for (int i = 1; i < NPTS; i++) {
            float dx = px[i] - px[0], dy = py[i] - py[0], dz = pz[i] - pz[0];
            float d2 = dx * dx + dy * dy + dz * dz;
            key[i] = d2;
            dmax2 = fmaxf(dmax2, d2);
        }
        float m1 = BIGF, m2 = BIGF;
#pragma unroll 1
        for (int it = 0; it < NEDGE; it++) {
#define MINP(AV, AI, BV, BI, OV, OI) \
            { bool c = (BV) < (AV); OV = c ? (BV) : (AV); OI = c ? (BI) : (AI); }
            float v12, v34, v56, v78, v910, v1112;
            int   i12, i34, i56, i78, i910, i1112;
            MINP(key[1], 1, key[2], 2, v12, i12)
            MINP(key[3], 3, key[4], 4, v34, i34)
            MINP(key[5], 5, key[6], 6, v56, i56)
            MINP(key[7], 7, key[8], 8, v78, i78)
            MINP(key[9], 9, key[10], 10, v910, i910)
            MINP(key[11], 11, key[12], 12, v1112, i1112)
            float va, vb, vc; int ia, ib, ic;
            MINP(v12, i12, v34, i34, va, ia)
            MINP(v56, i56, v78, i78, vb, ib)
            MINP(v910, i910, v1112, i1112, vc, ic)
            float vab; int iab;
            MINP(va, ia, vb, ib, vab, iab)
            float vcd; int icd;
            MINP(vc, ic, key[13], 13, vcd, icd)
            float bv; int bj;
            MINP(vab, iab, vcd, icd, bv, bj)
#undef MINP
            if (bv < m1) { m2 = m1; m1 = bv; } else if (bv < m2) { m2 = bv; }
            g_deaths0[it * B + b] = sqrtf(fmaxf(bv, 1e-24f));
            float qx = px[0], qy = py[0], qz = pz[0];
#pragma unroll
            for (int c = 1; c < NPTS; c++) {
                if (bj == c) { qx = px[c]; qy = py[c]; qz = pz[c]; }
            }
#pragma unroll
            for (int i = 1; i < NPTS; i++) {
                float dx = px[i] - qx, dy = py[i] - qy, dz = pz[i] - qz;
                float d2 = dx * dx + dy * dy + dz * dz;
                dmax2 = fmaxf(dmax2, d2);
                float nk = fminf(key[i], d2);
                key[i] = (i == bj || key[i] >= BIGF) ? BIGF : nk;
            }
        }
        float dmax = sqrtf(fmaxf(dmax2, 1e-24f));
        g_dmax[b] = dmax;
        float d0 = sqrtf(fmaxf(m1, 1e-24f));
        float d1 = sqrtf(fmaxf(m2, 1e-24f));
        float p0 = d1 - d0;
        g_p0[b] = p0;
        if (p0 > 0.f) s0 = p0;
        float p1b = (rb[b * NF1 + 1] - rb[b * NF1 + 0]) * dmax * 0.3f;
        float p1d = p1b + (rd[b * NF1 + 1] - rd[b * NF1 + 0]) * dmax * 0.4f;
        g_p1b[b] = p1b;
        g_p1d[b] = p1d;
        if (p1b > 0.f) s1 += p1b;
        if (p1d > 0.f) s1 += p1d;
        euler[b] = (float)(NEDGE - NF1);
    }
    __shared__ float s_e[2][4];
    int lane = tid & 31, wid = tid >> 5;
    int nw = blockDim.x >> 5;
    s0 = warp_red(s0);
    s1 = warp_red(s1);
    if (lane == 0) { s_e[0][wid] = s0; s_e[1][wid] = s1; }
    __syncthreads();
    if (wid == 0 && lane < 2) {
        float v = 0.f;
        for (int w = 0; w < nw; w++) v += s_e[lane][w];
        if (lane == 0) g_sp0[blockIdx.x] = v; else g_sp1[blockIdx.x] = v;
    }
}

// ---------------- k_diag: diag0 + diag1 + entropy + (last block) features --------
// Shared budget: 4 tables (37.4KB) + bp (0.5KB) + misc (~1.3KB) < 48KB.
// Fallback weights ALIAS the sP/sQ tables (mutually exclusive with fast path).
__global__ void __launch_bounds__(256)
k_diag(const float* __restrict__ W1, const float* __restrict__ b1,
       const float* __restrict__ W2, const float* __restrict__ b2,
       const float* __restrict__ rb, const float* __restrict__ rd,
       const float* __restrict__ W3, const float* __restrict__ b3,
       float* __restrict__ out, float* __restrict__ ent, int B, int nblkm) {
    __shared__ float  sbp0[H1], sbp1[H1];
    __shared__ __align__(16) float4 sA[NSEG * SROW4];
    __shared__ __align__(16) float4 sC[NSEG * SROW4];
    __shared__ __align__(16) float4 sP[NSEG * SROW4];   // fast: t-tables | fallback: sw + sW2t
    __shared__ __align__(16) float4 sQ[NSEG * SROW4];
    __shared__ __align__(16) float4 sb2v[8];
    __shared__ float s_part[8][H2];
    __shared__ float s_bc[2][8];
    __shared__ int s_last;
    float* sw   = (float*)sP;                 // fallback: H1*4 floats (1KB of sP)
    float* sW2t = (float*)sQ;                 // fallback: H2*H1 floats (8KB of sQ)
    int tid = threadIdx.x;
    int fast = g_fast;
    for (int i = tid; i < H1; i += blockDim.x) { sbp0[i] = g_bp0[i]; sbp1[i] = g_bp1[i]; }
    for (int i = tid; i < NSEG * SROW4; i += blockDim.x) {
        sA[i] = g_A4[i]; sC[i] = g_C4[i];
    }
    if (fast) {
        for (int i = tid; i < NSEG * SROW4; i += blockDim.x) {
            sP[i] = g_P4[i]; sQ[i] = g_Q4[i];
        }
    } else {
        for (int j = tid; j < H1; j += blockDim.x) {
            sw[j * 4 + 0] = W1[j];
            sw[j * 4 + 1] = W1[H1 + j];
            sw[j * 4 + 2] = b1[j];
            sw[j * 4 + 3] = 0.f;
        }
        for (int i = tid; i < H1 * H2; i += blockDim.x) {
            int j = i / H2, k = i % H2;
            sW2t[k * H1 + j] = W2[i];
        }
    }
    if (tid < 8) sb2v[tid] = ((const float4*)b2)[tid];
    __syncthreads();

    int lane = tid & 31, wid = tid >> 5;
    int nw = blockDim.x >> 5;
    int stride = gridDim.x * blockDim.x;
    int gbase = blockIdx.x * blockDim.x + tid;
    float4 z = make_float4(0.f, 0.f, 0.f, 0.f);

    // ================= phase A: diag0 over MST deaths (float4 loads) =================
    {
        float4 a0 = z, a1 = z, a2 = z, a3 = z, a4 = z, a5 = z, a6 = z, a7 = z;
        int total = NEDGE * B;
        int total4 = total >> 2;
        if (fast) {
            int lo = 0, hi = H1;
#pragma unroll
            for (int s = 0; s < 6; s++) {
                int mid = (lo + hi) >> 1;
                if (sbp0[mid] < 1e-20f) lo = mid + 1; else hi = mid;
            }
            const float4* Av = sA + lo * SROW4;
            const float4* Cv = sC + lo * SROW4;
            float4 A0 = Av[0], A1 = Av[1], A2 = Av[2], A3 = Av[3];
            float4 A4 = Av[4], A5 = Av[5], A6 = Av[6], A7 = Av[7];
            float4 C0 = Cv[0], C1 = Cv[1], C2 = Cv[2], C3 = Cv[3];
            float4 C4 = Cv[4], C5 = Cv[5], C6 = Cv[6], C7 = Cv[7];
            const float4* dp = (const float4*)g_deaths0;
#define Q0(ACC, AV, CV, D) {                                              \
            ACC.x += fmaxf(fmaf(AV.x, D, CV.x), 0.f);                     \
            ACC.y += fmaxf(fmaf(AV.y, D, CV.y), 0.f);                     \
            ACC.z += fmaxf(fmaf(AV.z, D, CV.z), 0.f);                     \
            ACC.w += fmaxf(fmaf(AV.w, D, CV.w), 0.f); }
#define QALL(D) { Q0(a0, A0, C0, D) Q0(a1, A1, C1, D) Q0(a2, A2, C2, D)   \
                  Q0(a3, A3, C3, D) Q0(a4, A4, C4, D) Q0(a5, A5, C5, D)   \
                  Q0(a6, A6, C6, D) Q0(a7, A7, C7, D) }
            for (int i4 = gbase; i4 < total4; i4 += stride) {
                float4 d4 = dp[i4];
                QALL(d4.x) QALL(d4.y) QALL(d4.z) QALL(d4.w)
            }
            for (int i = (total4 << 2) + gbase; i < total; i += stride) {
                float d = g_deaths0[i];
                QALL(d)
            }
#undef QALL
#undef Q0
        } else {
            for (int i = gbase; i < total; i += stride) {
                float d = g_deaths0[i];
                int lo = 0, hi = H1;
#pragma unroll
                for (int s = 0; s < 6; s++) {
                    int mid = (lo + hi) >> 1;
                    if (sbp0[mid] < d) lo = mid + 1; else hi = mid;
                }
                const float4* Av = sA + lo * SROW4;
                const float4* Cv = sC + lo * SROW4;
#define Q1(ACC, q) { float4 A = Av[q], C = Cv[q];                         \
                ACC.x += fmaxf(fmaf(A.x, d, C.x), 0.f);                   \
                ACC.y += fmaxf(fmaf(A.y, d, C.y), 0.f);                   \
                ACC.z += fmaxf(fmaf(A.z, d, C.z), 0.f);                   \
                ACC.w += fmaxf(fmaf(A.w, d, C.w), 0.f); }
                Q1(a0, 0) Q1(a1, 1) Q1(a2, 2) Q1(a3, 3)
                Q1(a4, 4) Q1(a5, 5) Q1(a6, 6) Q1(a7, 7)
#undef Q1
            }
        }
#define R(ACC, q) {                                                        \
        float vx = warp_red(ACC.x), vy = warp_red(ACC.y);                  \
        float vz = warp_red(ACC.z), vw = warp_red(ACC.w);                  \
        if (lane == 0) { s_part[wid][q * 4 + 0] = vx; s_part[wid][q * 4 + 1] = vy; \
                         s_part[wid][q * 4 + 2] = vz; s_part[wid][q * 4 + 3] = vw; } }
        R(a0, 0) R(a1, 1) R(a2, 2) R(a3, 3) R(a4, 4) R(a5, 5) R(a6, 6) R(a7, 7)
        __syncthreads();
        if (tid < H2) {
            float v = 0.f;
            for (int w = 0; w < nw; w++) v += s_part[w][tid];
            g_h2p0[blockIdx.x * H2 + tid] = v;
        }
        __syncthreads();
    }

    // ================= phase B: diag1 over random features =================
    {
        float4 c0 = z, c1 = z, c2 = z, c3 = z, c4 = z, c5 = z, c6 = z, c7 = z;
        int total = NF1 * B;
        if (fast) {
            float4 B0 = sb2v[0], B1 = sb2v[1], B2 = sb2v[2], B3 = sb2v[3];
            float4 B4 = sb2v[4], B5 = sb2v[5], B6 = sb2v[6], B7 = sb2v[7];
            for (int i = gbase; i < total; i += stride) {
                float dm = g_dmax[i / NF1];
                float x = rb[i] * dm * 0.3f;
                float y = fmaf(rd[i] * dm, 0.4f, x);
                float t = (y > 0.f) ? (x / y) : 0.f;
                int lo = 0, hi = H1;
#pragma unroll
                for (int s = 0; s < 6; s++) {
                    int mid = (lo + hi) >> 1;
                    if (sbp1[mid] < t) lo = mid + 1; else hi = mid;
                }
                const float4* Pv = sP + lo * SROW4;
                const float4* Qv = sQ + lo * SROW4;
#define Q2(ACC, q, BV) { float4 P = Pv[q], Q = Qv[q];                      \
                ACC.x += fmaxf(fmaf(y, fmaf(P.x, t, Q.x), BV.x), 0.f);     \
                ACC.y += fmaxf(fmaf(y, fmaf(P.y, t, Q.y), BV.y), 0.f);     \
                ACC.z += fmaxf(fmaf(y, fmaf(P.z, t, Q.z), BV.z), 0.f);     \
                ACC.w += fmaxf(fmaf(y, fmaf(P.w, t, Q.w), BV.w), 0.f); }
                Q2(c0, 0, B0) Q2(c1, 1, B1) Q2(c2, 2, B2) Q2(c3, 3, B3)
                Q2(c4, 4, B4) Q2(c5, 5, B5) Q2(c6, 6, B6) Q2(c7, 7, B7)
#undef Q2
            }
        } else {
            for (int i = gbase; i < total; i += stride) {
                float dm = g_dmax[i / NF1];
                float x = rb[i] * dm * 0.3f;
                float y = fmaf(rd[i] * dm, 0.4f, x);
                float4 t0 = sb2v[0], t1 = sb2v[1], t2 = sb2v[2], t3 = sb2v[3];
                float4 t4 = sb2v[4], t5 = sb2v[5], t6 = sb2v[6], t7 = sb2v[7];
#pragma unroll 1
                for (int jc = 0; jc < 4; jc++) {
                    const float4* swv = (const float4*)sw + jc * 16;
                    float4 ha, hb, hc, hd;
#define HV(DST, COMP, IDX) { float4 w = swv[IDX];                              \
                    DST.COMP = fmaxf(fmaf(x, w.x, fmaf(y, w.y, w.z)), 0.f); }
                    HV(ha, x, 0)  HV(ha, y, 1)  HV(ha, z, 2)  HV(ha, w, 3)
                    HV(hb, x, 4)  HV(hb, y, 5)  HV(hb, z, 6)  HV(hb, w, 7)
                    HV(hc, x, 8)  HV(hc, y, 9)  HV(hc, z, 10) HV(hc, w, 11)
                    HV(hd, x, 12) HV(hd, y, 13) HV(hd, z, 14) HV(hd, w, 15)
#undef HV
                    const float* wb = sW2t + jc * 16;
                    t0.x += dot16(ha, hb, hc, hd, wb + 0 * H1);
                    t0.y += dot16(ha, hb, hc, hd, wb + 1 * H1);
                    t0.z += dot16(ha, hb, hc, hd, wb + 2 * H1);
                    t0.w += dot16(ha, hb, hc, hd, wb + 3 * H1);
                    t1.x += dot16(ha, hb, hc, hd, wb + 4 * H1);
                    t1.y += dot16(ha, hb, hc, hd, wb + 5 * H1);
                    t1.z += dot16(ha, hb, hc, hd, wb + 6 * H1);
                    t1.w += dot16(ha, hb, hc, hd, wb + 7 * H1);
                    t2.x += dot16(ha, hb, hc, hd, wb + 8 * H1);
                    t2.y += dot16(ha, hb, hc, hd, wb + 9 * H1);
                    t2.z += dot16(ha, hb, hc, hd, wb + 10 * H1);
                    t2.w += dot16(ha, hb, hc, hd, wb + 11 * H1);
                    t3.x += dot16(ha, hb, hc, hd, wb + 12 * H1);
                    t3.y += dot16(ha, hb, hc, hd, wb + 13 * H1);
                    t3.z += dot16(ha, hb, hc, hd, wb + 14 * H1);
                    t3.w += dot16(ha, hb, hc, hd, wb + 15 * H1);
                    t4.x += dot16(ha, hb, hc, hd, wb + 16 * H1);
                    t4.y += dot16(ha, hb, hc, hd, wb + 17 * H1);
                    t4.z += dot16(ha, hb, hc, hd, wb + 18 * H1);
                    t4.w += dot16(ha, hb, hc, hd, wb + 19 * H1);
                    t5.x += dot16(ha, hb, hc, hd, wb + 20 * H1);
                    t5.y += dot16(ha, hb, hc, hd, wb + 21 * H1);
                    t5.z += dot16(ha, hb, hc, hd, wb + 22 * H1);
                    t5.w += dot16(ha, hb, hc, hd, wb + 23 * H1);
                    t6.x += dot16(ha, hb, hc, hd, wb + 24 * H1);
                    t6.y += dot16(ha, hb, hc, hd, wb + 25 * H1);
                    t6.z += dot16(ha, hb, hc, hd, wb + 26 * H1);
                    t6.w += dot16(ha, hb, hc, hd, wb + 27 * H1);
                    t7.x += dot16(ha, hb, hc, hd, wb + 28 * H1);
                    t7.y += dot16(ha, hb, hc, hd, wb + 29 * H1);
                    t7.z += dot16(ha, hb, hc, hd, wb + 30 * H1);
                    t7.w += dot16(ha, hb, hc, hd, wb + 31 * H1);
                }
#define EP(TP, ACC) { ACC.x += fmaxf(TP.x, 0.f); ACC.y += fmaxf(TP.y, 0.f);    \
                      ACC.z += fmaxf(TP.z, 0.f); ACC.w += fmaxf(TP.w, 0.f); }
                EP(t0, c0) EP(t1, c1) EP(t2, c2) EP(t3, c3)
                EP(t4, c4) EP(t5, c5) EP(t6, c6) EP(t7, c7)
#undef EP
            }
        }
        R(c0, 0) R(c1, 1) R(c2, 2) R(c3, 3) R(c4, 4) R(c5, 5) R(c6, 6) R(c7, 7)
#undef R
        __syncthreads();
        if (tid < H2) {
            float v = 0.f;
            for (int w = 0; w < nw; w++) v += s_part[w][tid];
            g_h2p1[blockIdx.x * H2 + tid] = v;
        }
        __syncthreads();
    }

    // ================= phase C: entropy (needs mst partials) =================
    {
        float s0 = 0.f, s1 = 0.f;
        for (int i = tid; i < nblkm; i += blockDim.x) { s0 += g_sp0[i]; s1 += g_sp1[i]; }
        s0 = warp_red(s0); s1 = warp_red(s1);
        if (lane == 0) { s_bc[0][wid] = s0; s_bc[1][wid] = s1; }
        __syncthreads();
        float S0 = 0.f, S1 = 0.f;
        for (int w = 0; w < nw; w++) { S0 += s_bc[0][w]; S1 += s_bc[1][w]; }
        S0 = fmaxf(S0, 1e-30f); S1 = fmaxf(S1, 1e-30f);
        float e = 0.f;
        for (int bb = gbase; bb < B; bb += stride) {
            float p = g_p0[bb];
            if (p > 0.f)  { float q = p  / S0; e -= q * logf(q + 1e-10f); }
            float pb = g_p1b[bb];
            if (pb > 0.f) { float q = pb / S1; e -= q * logf(q + 1e-10f); }
            float pd = g_p1d[bb];
            if (pd > 0.f) { float q = pd / S1; e -= q * logf(q + 1e-10f); }
        }
        e = warp_red(e);
        if (lane == 0) s_part[wid][0] = e;
        __syncthreads();
        if (tid == 0) {
            float v = 0.f;
            for (int w = 0; w < nw; w++) v += s_part[w][0];
            g_epart[blockIdx.x] = v;
        }
    }

    // ================= last block: features + entropy write =================
    __threadfence();
    if (tid == 0) s_last = (atomicAdd(&g_done, 1) == (int)gridDim.x - 1) ? 1 : 0;
    __syncthreads();
    if (s_last) {
        __shared__ float u[H2];
        // parallel reduction of DIAGG x H2 partials, staged in dead sA region
        float* rbuf = (float*)sA;                   // 512 floats (sA is dead now)
        {
            int k = tid & 31, chunk = tid >> 5;     // 8 chunks x 32 k
            float v0 = 0.f, v1 = 0.f;
            for (int blk = chunk; blk < DIAGG; blk += 8) {
                v0 += g_h2p0[blk * H2 + k];
                v1 += g_h2p1[blk * H2 + k];
            }
            rbuf[chunk * H2 + k] = v0;
            rbuf[256 + chunk * H2 + k] = v1;
        }
        __syncthreads();
        if (tid < H2) {
            float v0 = 0.f, v1 = 0.f;
#pragma unroll
            for (int c = 0; c < 8; c++) {
                v0 += rbuf[c * H2 + tid];
                v1 += rbuf[256 + c * H2 + tid];
            }
            u[tid] = v0 / ((float)NEDGE * (float)B) + v1 / ((float)NF1 * (float)B);
        }
        __syncthreads();
        for (int f = tid; f < FDIM; f += blockDim.x) {
            float t = 2.f * b3[f];
#pragma unroll
            for (int k = 0; k < H2; k++) t += u[k] * W3[k * FDIM + f];
            out[f] = t;
        }
        {
            float v = 0.f;
            for (int i = tid; i < DIAGG; i += blockDim.x) v += g_epart[i];
            v = warp_red(v);
            if (lane == 0) s_part[wid][1] = v;
            __syncthreads();
            if (tid == 0) {
                float tot = 0.f;
                for (int w = 0; w < nw; w++) tot += s_part[w][1];
                *ent = tot;
                g_done = 0;   // reset for next graph replay
            }
        }
    }
}

// ---------------- launch ----------------
extern "C" void kernel_launch(void* const* d_in, const int* in_sizes, int n_in,
                              void* d_out, int out_size) {
    const float* pc = (const float*)d_in[0];
    const float* rb = (const float*)d_in[1];
    const float* rd = (const float*)d_in[2];
    const float* W1 = (const float*)d_in[3];
    const float* b1 = (const float*)d_in[4];
    const float* W2 = (const float*)d_in[5];
    const float* b2 = (const float*)d_in[6];
    const float* W3 = (const float*)d_in[7];
    const float* b3 = (const float*)d_in[8];
    float* out = (float*)d_out;

    int B = in_sizes[1] / NF1;
    if (B > BMAX) B = BMAX;
    int nblkm = (B + 127) / 128;

    float* euler = out + FDIM;
    float* ent   = out + FDIM + B;

    k_mst<<<nblkm + NTBLK, 128>>>(pc, rb, rd, W1, b1, W2, b2, euler, B);
    k_diag<<<DIAGG, 256>>>(W1, b1, W2, b2, rb, rd, W3, b3, out, ent, B, nblkm);
}

// round 16
// speedup vs baseline: 1.3026x; 1.1371x over previous
#include <cuda_runtime.h>
#include <math.h>

#define NPTS  14
#define NEDGE 13
#define NF1   3
#define BMAX  65536
#define FDIM  512
#define H1    64
#define H2    32
#define NSEG  (H1 + 1)
#define SROW4 9            // 9 float4 = 36 floats padded row
#define BIGF  1e30f
#define DIAGG 592          // diag grid (4 blocks/SM)
#define MSTB  520          // max mst blocks
#define NTBLK 16           // table-builder blocks

// ---------------- scratch (all write-once per launch; no zero-init needed) --------
__device__ float  g_deaths0[NEDGE * BMAX];
__device__ float  g_dmax[BMAX];
__device__ float  g_p0[BMAX];
__device__ float  g_p1b[BMAX];
__device__ float  g_p1d[BMAX];
__device__ float  g_sp0[MSTB];
__device__ float  g_sp1[MSTB];
__device__ float  g_h2p0[DIAGG * H2];
__device__ float  g_h2p1[DIAGG * H2];
__device__ float  g_epart[DIAGG];
__device__ float  g_bp0[H1];
__device__ float  g_bp1[H1];
__device__ float4 g_A4[NSEG * SROW4];
__device__ float4 g_C4[NSEG * SROW4];
__device__ float4 g_P4[NSEG * SROW4];
__device__ float4 g_Q4[NSEG * SROW4];
__device__ int    g_fast;
__device__ int    g_done = 0;

__device__ __forceinline__ float warp_red(float v) {
#pragma unroll
    for (int o = 16; o; o >>= 1) v += __shfl_xor_sync(0xffffffffu, v, o);
    return v;
}

// 16-wide dot (fallback path)
__device__ __forceinline__ float dot16(float4 ha, float4 hb, float4 hc, float4 hd,
                                       const float* base) {
    const float4* wv = (const float4*)base;
    float4 w0 = wv[0], w1 = wv[1], w2 = wv[2], w3 = wv[3];
    float s;
    s = ha.x * w0.x;
    s = fmaf(ha.y, w0.y, s); s = fmaf(ha.z, w0.z, s); s = fmaf(ha.w, w0.w, s);
    s = fmaf(hb.x, w1.x, s); s = fmaf(hb.y, w1.y, s); s = fmaf(hb.z, w1.z, s); s = fmaf(hb.w, w1.w, s);
    s = fmaf(hc.x, w2.x, s); s = fmaf(hc.y, w2.y, s); s = fmaf(hc.z, w2.z, s); s = fmaf(hc.w, w2.w, s);
    s = fmaf(hd.x, w3.x, s); s = fmaf(hd.y, w3.y, s); s = fmaf(hd.z, w3.z, s); s = fmaf(hd.w, w3.w, s);
    return s;
}

// ---------------- k_mst: MST blocks (direct loads) + NTBLK table builders --------
__global__ void __launch_bounds__(128)
k_mst(const float* __restrict__ pc, const float* __restrict__ rb,
      const float* __restrict__ rd,
      const float* __restrict__ W1, const float* __restrict__ b1,
      const float* __restrict__ W2, const float* __restrict__ b2,
      float* __restrict__ euler, int B) {
    int nblkm = gridDim.x - NTBLK;
    int tid = threadIdx.x;
    const float INF = __int_as_float(0x7f800000);

    if ((int)blockIdx.x >= nblkm) {
        // ======== table-builder blocks: weights staged in shared ========
        int rel = blockIdx.x - nblkm;            // 0..NTBLK-1
        __shared__ float sW1[2 * H1], sb1s[H1], sW2s[H1 * H2], sb2s[H2];
        __shared__ float sb0[H1], sb1b[H1], st[H1];
        __shared__ int s_nz;
        if (tid == 0) s_nz = 0;
        for (int i = tid; i < 2 * H1; i += blockDim.x) sW1[i] = W1[i];
        for (int i = tid; i < H1; i += blockDim.x) sb1s[i] = b1[i];
        for (int i = tid; i < H1 * H2; i += blockDim.x) sW2s[i] = W2[i];
        for (int i = tid; i < H2; i += blockDim.x) sb2s[i] = b2[i];
        __syncthreads();
        if (tid < H1) {
            float w = sW1[H1 + tid];
            st[tid] = (w != 0.f) ? (-sb1s[tid] / w) : INF;
            if (sb1s[tid] != 0.f) atomicAdd(&s_nz, 1);
        }
        __syncthreads();
        if (tid < H1) {
            float t = st[tid];
            int r = 0;
#pragma unroll
            for (int i = 0; i < H1; i++) {
                float ti = st[i];
                r += (ti < t || (ti == t && i < tid)) ? 1 : 0;
            }
            sb0[r] = t;
            if (rel == 0) g_bp0[r] = t;
        }
        __syncthreads();
        if (tid < H1) {
            float w0 = sW1[tid], w1 = sW1[H1 + tid];
            st[tid] = (w0 != 0.f) ? (-w1 / w0) : INF;
        }
        __syncthreads();
        if (tid < H1) {
            float t = st[tid];
            int r = 0;
#pragma unroll
            for (int i = 0; i < H1; i++) {
                float ti = st[i];
                r += (ti < t || (ti == t && i < tid)) ? 1 : 0;
            }
            sb1b[r] = t;
            if (rel == 0) g_bp1[r] = t;
        }
        if (rel == 0 && tid == 0) g_fast = (s_nz == 0) ? 1 : 0;
        __syncthreads();
        int gt = rel * 128 + tid;                // 0..NTBLK*128-1
        for (int e = gt; e < NSEG * H2; e += NTBLK * 128) {
            int s = e >> 5, k = e & 31;
            {   // diag0 tables (segment in d)
                float lo = (s == 0)  ? -INF : sb0[s - 1];
                float hi = (s == H1) ?  INF : sb0[s];
                float rep;
                bool li = isinf(lo), hiinf = isinf(hi);
                if (li && hiinf)      rep = 0.f;
                else if (li)          rep = hi - 1.f;
                else if (hiinf)       rep = lo + 1.f;
                else                  rep = 0.5f * (lo + hi);
                float A = 0.f, C = sb2s[k];
#pragma unroll 1
                for (int j = 0; j < H1; j++) {
                    float w = sW1[H1 + j], bb = sb1s[j];
                    bool act = (w == 0.f) ? (bb > 0.f) : ((w * rep + bb) > 0.f);
                    if (act) {
                        float m = sW2s[j * H2 + k];
                        A += w * m;
                        C += bb * m;
                    }
                }
                ((float*)g_A4)[s * (SROW4 * 4) + k] = A;
                ((float*)g_C4)[s * (SROW4 * 4) + k] = C;
            }
            {   // diag1 tables (segment in t = x/y)
                float lo = (s == 0)  ? -INF : sb1b[s - 1];
                float hi = (s == H1) ?  INF : sb1b[s];
                float rep;
                bool li = isinf(lo), hiinf = isinf(hi);
                if (li && hiinf)      rep = 0.f;
                else if (li)          rep = hi - 1.f;
                else if (hiinf)       rep = lo + 1.f;
                else                  rep = 0.5f * (lo + hi);
                float P = 0.f, Q = 0.f;
#pragma unroll 1
                for (int j = 0; j < H1; j++) {
                    float w0 = sW1[j], w1 = sW1[H1 + j];
                    bool act = (w0 == 0.f) ? (w1 > 0.f) : ((w0 * rep + w1) > 0.f);
                    if (act) {
                        float m = sW2s[j * H2 + k];
                        P += w0 * m;
                        Q += w1 * m;
                    }
                }
                ((float*)g_P4)[s * (SROW4 * 4) + k] = P;
                ((float*)g_Q4)[s * (SROW4 * 4) + k] = Q;
            }
        }
        return;
    }

    // ======== MST blocks (direct global loads, no staging) ========
    int b = blockIdx.x * blockDim.x + tid;
    float s0 = 0.f, s1 = 0.f;
    if (b < B) {
        const float* p = pc + (long long)b * (NPTS * 3);
        float px[NPTS], py[NPTS], pz[NPTS];
#pragma unroll
        for (int i = 0; i < NPTS; i++) {
            px[i] = p[3 * i]; py[i] = p[3 * i + 1]; pz[i] = p[3 * i + 2];
        }
        float key[NPTS];
        float dmax2 = 0.f;
        key[0] = BIGF;
#pragma unroll
        for (int i = 1; i < NPTS; i++) {
            float dx = px[i] - px[0], dy = py[i] - py[0], dz = pz[i] - pz[0];
            float d2 = dx * dx + dy * dy + dz * dz;
            key[i] = d2;
            dmax2 = fmaxf(dmax2, d2);
        }
        float m1 = BIGF, m2 = BIGF;
#pragma unroll 1
        for (int it = 0; it < NEDGE; it++) {
#define MINP(AV, AI, BV, BI, OV, OI) \
            { bool c = (BV) < (AV); OV = c ? (BV) : (AV); OI = c ? (BI) : (AI); }
            float v12, v34, v56, v78, v910, v1112;
            int   i12, i34, i56, i78, i910, i1112;
            MINP(key[1], 1, key[2], 2, v12, i12)
            MINP(key[3], 3, key[4], 4, v34, i34)
            MINP(key[5], 5, key[6], 6, v56, i56)
            MINP(key[7], 7, key[8], 8, v78, i78)
            MINP(key[9], 9, key[10], 10, v910, i910)
            MINP(key[11], 11, key[12], 12, v1112, i1112)
            float va, vb, vc; int ia, ib, ic;
            MINP(v12, i12, v34, i34, va, ia)
            MINP(v56, i56, v78, i78, vb, ib)
            MINP(v910, i910, v1112, i1112, vc, ic)
            float vab; int iab;
            MINP(va, ia, vb, ib, vab, iab)
            float vcd; int icd;
            MINP(vc, ic, key[13], 13, vcd, icd)
            float bv; int bj;
            MINP(vab, iab, vcd, icd, bv, bj)
#undef MINP
            if (bv < m1) { m2 = m1; m1 = bv; } else if (bv < m2) { m2 = bv; }
            g_deaths0[it * B + b] = sqrtf(fmaxf(bv, 1e-24f));
            float qx = px[0], qy = py[0], qz = pz[0];
#pragma unroll
            for (int c = 1; c < NPTS; c++) {
                if (bj == c) { qx = px[c]; qy = py[c]; qz = pz[c]; }
            }
#pragma unroll
            for (int i = 1; i < NPTS; i++) {
                float dx = px[i] - qx, dy = py[i] - qy, dz = pz[i] - qz;
                float d2 = dx * dx + dy * dy + dz * dz;
                dmax2 = fmaxf(dmax2, d2);
                float nk = fminf(key[i], d2);
                key[i] = (i == bj || key[i] >= BIGF) ? BIGF : nk;
            }
        }
        float dmax = sqrtf(fmaxf(dmax2, 1e-24f));
        g_dmax[b] = dmax;
        float d0 = sqrtf(fmaxf(m1, 1e-24f));
        float d1 = sqrtf(fmaxf(m2, 1e-24f));
        float p0 = d1 - d0;
        g_p0[b] = p0;
        if (p0 > 0.f) s0 = p0;
        float p1b = (rb[b * NF1 + 1] - rb[b * NF1 + 0]) * dmax * 0.3f;
        float p1d = p1b + (rd[b * NF1 + 1] - rd[b * NF1 + 0]) * dmax * 0.4f;
        g_p1b[b] = p1b;
        g_p1d[b] = p1d;
        if (p1b > 0.f) s1 += p1b;
        if (p1d > 0.f) s1 += p1d;
        euler[b] = (float)(NEDGE - NF1);
    }
    __shared__ float s_e[2][4];
    int lane = tid & 31, wid = tid >> 5;
    int nw = blockDim.x >> 5;
    s0 = warp_red(s0);
    s1 = warp_red(s1);
    if (lane == 0) { s_e[0][wid] = s0; s_e[1][wid] = s1; }
    __syncthreads();
    if (wid == 0 && lane < 2) {
        float v = 0.f;
        for (int w = 0; w < nw; w++) v += s_e[lane][w];
        if (lane == 0) g_sp0[blockIdx.x] = v; else g_sp1[blockIdx.x] = v;
    }
}

// ---------------- k_diag: diag0 + diag1 + entropy + (last block) features --------
// Fallback weights ALIAS the sP/sQ tables (mutually exclusive with fast path).
__global__ void __launch_bounds__(256)
k_diag(const float* __restrict__ W1, const float* __restrict__ b1,
       const float* __restrict__ W2, const float* __restrict__ b2,
       const float* __restrict__ rb, const float* __restrict__ rd,
       const float* __restrict__ W3, const float* __restrict__ b3,
       float* __restrict__ out, float* __restrict__ ent, int B, int nblkm) {
    __shared__ float  sbp0[H1], sbp1[H1];
    __shared__ __align__(16) float4 sA[NSEG * SROW4];
    __shared__ __align__(16) float4 sC[NSEG * SROW4];
    __shared__ __align__(16) float4 sP[NSEG * SROW4];   // fast: t-tables | fallback: sw + sW2t
    __shared__ __align__(16) float4 sQ[NSEG * SROW4];
    __shared__ __align__(16) float4 sb2v[8];
    __shared__ float s_part[8][H2];
    __shared__ float s_bc[2][8];
    __shared__ int s_last;
    float* sw   = (float*)sP;                 // fallback: H1*4 floats
    float* sW2t = (float*)sQ;                 // fallback: H2*H1 floats
    int tid = threadIdx.x;
    int fast = g_fast;
    for (int i = tid; i < H1; i += blockDim.x) { sbp0[i] = g_bp0[i]; sbp1[i] = g_bp1[i]; }
    for (int i = tid; i < NSEG * SROW4; i += blockDim.x) {
        sA[i] = g_A4[i]; sC[i] = g_C4[i];
    }
    if (fast) {
        for (int i = tid; i < NSEG * SROW4; i += blockDim.x) {
            sP[i] = g_P4[i]; sQ[i] = g_Q4[i];
        }
    } else {
        for (int j = tid; j < H1; j += blockDim.x) {
            sw[j * 4 + 0] = W1[j];
            sw[j * 4 + 1] = W1[H1 + j];
            sw[j * 4 + 2] = b1[j];
            sw[j * 4 + 3] = 0.f;
        }
        for (int i = tid; i < H1 * H2; i += blockDim.x) {
            int j = i / H2, k = i % H2;
            sW2t[k * H1 + j] = W2[i];
        }
    }
    if (tid < 8) sb2v[tid] = ((const float4*)b2)[tid];
    __syncthreads();

    int lane = tid & 31, wid = tid >> 5;
    int nw = blockDim.x >> 5;
    int stride = gridDim.x * blockDim.x;
    int gbase = blockIdx.x * blockDim.x + tid;
    float4 z = make_float4(0.f, 0.f, 0.f, 0.f);

    // ================= phase A: diag0 over MST deaths (float4 loads) =================
    {
        float4 a0 = z, a1 = z, a2 = z, a3 = z, a4 = z, a5 = z, a6 = z, a7 = z;
        int total = NEDGE * B;
        int total4 = total >> 2;
        if (fast) {
            int lo = 0, hi = H1;
#pragma unroll
            for (int s = 0; s < 6; s++) {
                int mid = (lo + hi) >> 1;
                if (sbp0[mid] < 1e-20f) lo = mid + 1; else hi = mid;
            }
            const float4* Av = sA + lo * SROW4;
            const float4* Cv = sC + lo * SROW4;
            float4 A0 = Av[0], A1 = Av[1], A2 = Av[2], A3 = Av[3];
            float4 A4 = Av[4], A5 = Av[5], A6 = Av[6], A7 = Av[7];
            float4 C0 = Cv[0], C1 = Cv[1], C2 = Cv[2], C3 = Cv[3];
            float4 C4 = Cv[4], C5 = Cv[5], C6 = Cv[6], C7 = Cv[7];
            const float4* dp = (const float4*)g_deaths0;
#define Q0(ACC, AV, CV, D) {                                              \
            ACC.x += fmaxf(fmaf(AV.x, D, CV.x), 0.f);                     \
            ACC.y += fmaxf(fmaf(AV.y, D, CV.y), 0.f);                     \
            ACC.z += fmaxf(fmaf(AV.z, D, CV.z), 0.f);                     \
            ACC.w += fmaxf(fmaf(AV.w, D, CV.w), 0.f); }
#define QALL(D) { Q0(a0, A0, C0, D) Q0(a1, A1, C1, D) Q0(a2, A2, C2, D)   \
                  Q0(a3, A3, C3, D) Q0(a4, A4, C4, D) Q0(a5, A5, C5, D)   \
                  Q0(a6, A6, C6, D) Q0(a7, A7, C7, D) }
            for (int i4 = gbase; i4 < total4; i4 += stride) {
                float4 d4 = dp[i4];
                QALL(d4.x) QALL(d4.y) QALL(d4.z) QALL(d4.w)
            }
            for (int i = (total4 << 2) + gbase; i < total; i += stride) {
                float d = g_deaths0[i];
                QALL(d)
            }
#undef QALL
#undef Q0
        } else {
            for (int i = gbase; i < total; i += stride) {
                float d = g_deaths0[i];
                int lo = 0, hi = H1;
#pragma unroll
                for (int s = 0; s < 6; s++) {
                    int mid = (lo + hi) >> 1;
                    if (sbp0[mid] < d) lo = mid + 1; else hi = mid;
                }
                const float4* Av = sA + lo * SROW4;
                const float4* Cv = sC + lo * SROW4;
#define Q1(ACC, q) { float4 A = Av[q], C = Cv[q];                         \
                ACC.x += fmaxf(fmaf(A.x, d, C.x), 0.f);                   \
                ACC.y += fmaxf(fmaf(A.y, d, C.y), 0.f);                   \
                ACC.z += fmaxf(fmaf(A.z, d, C.z), 0.f);                   \
                ACC.w += fmaxf(fmaf(A.w, d, C.w), 0.f); }
                Q1(a0, 0) Q1(a1, 1) Q1(a2, 2) Q1(a3, 3)
                Q1(a4, 4) Q1(a5, 5) Q1(a6, 6) Q1(a7, 7)
#undef Q1
            }
        }
#define R(ACC, q) {                                                        \
        float vx = warp_red(ACC.x), vy = warp_red(ACC.y);                  \
        float vz = warp_red(ACC.z), vw = warp_red(ACC.w);                  \
        if (lane == 0) { s_part[wid][q * 4 + 0] = vx; s_part[wid][q * 4 + 1] = vy; \
                         s_part[wid][q * 4 + 2] = vz; s_part[wid][q * 4 + 3] = vw; } }
        R(a0, 0) R(a1, 1) R(a2, 2) R(a3, 3) R(a4, 4) R(a5, 5) R(a6, 6) R(a7, 7)
        __syncthreads();
        if (tid < H2) {
            float v = 0.f;
            for (int w = 0; w < nw; w++) v += s_part[w][tid];
            g_h2p0[blockIdx.x * H2 + tid] = v;
        }
        __syncthreads();
    }

    // ================= phase B: diag1 over random features =================
    {
        float4 c0 = z, c1 = z, c2 = z, c3 = z, c4 = z, c5 = z, c6 = z, c7 = z;
        int total = NF1 * B;
        if (fast) {
            float4 B0 = sb2v[0], B1 = sb2v[1], B2 = sb2v[2], B3 = sb2v[3];
            float4 B4 = sb2v[4], B5 = sb2v[5], B6 = sb2v[6], B7 = sb2v[7];
            for (int i = gbase; i < total; i += stride) {
                float dm = g_dmax[i / NF1];
                float x = rb[i] * dm * 0.3f;
                float y = fmaf(rd[i] * dm, 0.4f, x);
                float t = (y > 0.f) ? (x / y) : 0.f;
                int lo = 0, hi = H1;
#pragma unroll
                for (int s = 0; s < 6; s++) {
                    int mid = (lo + hi) >> 1;
                    if (sbp1[mid] < t) lo = mid + 1; else hi = mid;
                }
                const float4* Pv = sP + lo * SROW4;
                const float4* Qv = sQ + lo * SROW4;
#define Q2(ACC, q, BV) { float4 P = Pv[q], Q = Qv[q];                      \
                ACC.x += fmaxf(fmaf(y, fmaf(P.x, t, Q.x), BV.x), 0.f);     \
                ACC.y += fmaxf(fmaf(y, fmaf(P.y, t, Q.y), BV.y), 0.f);     \
                ACC.z += fmaxf(fmaf(y, fmaf(P.z, t, Q.z), BV.z), 0.f);     \
                ACC.w += fmaxf(fmaf(y, fmaf(P.w, t, Q.w), BV.w), 0.f); }
                Q2(c0, 0, B0) Q2(c1, 1, B1) Q2(c2, 2, B2) Q2(c3, 3, B3)
                Q2(c4, 4, B4) Q2(c5, 5, B5) Q2(c6, 6, B6) Q2(c7, 7, B7)
#undef Q2
            }
        } else {
            for (int i = gbase; i < total; i += stride) {
                float dm = g_dmax[i / NF1];
                float x = rb[i] * dm * 0.3f;
                float y = fmaf(rd[i] * dm, 0.4f, x);
                float4 t0 = sb2v[0], t1 = sb2v[1], t2 = sb2v[2], t3 = sb2v[3];
                float4 t4 = sb2v[4], t5 = sb2v[5], t6 = sb2v[6], t7 = sb2v[7];
#pragma unroll 1
                for (int jc = 0; jc < 4; jc++) {
                    const float4* swv = (const float4*)sw + jc * 16;
                    float4 ha, hb, hc, hd;
#define HV(DST, COMP, IDX) { float4 w = swv[IDX];                              \
                    DST.COMP = fmaxf(fmaf(x, w.x, fmaf(y, w.y, w.z)), 0.f); }
                    HV(ha, x, 0)  HV(ha, y, 1)  HV(ha, z, 2)  HV(ha, w, 3)
                    HV(hb, x, 4)  HV(hb, y, 5)  HV(hb, z, 6)  HV(hb, w, 7)
                    HV(hc, x, 8)  HV(hc, y, 9)  HV(hc, z, 10) HV(hc, w, 11)
                    HV(hd, x, 12) HV(hd, y, 13) HV(hd, z, 14) HV(hd, w, 15)
#undef HV
                    const float* wb = sW2t + jc * 16;
                    t0.x += dot16(ha, hb, hc, hd, wb + 0 * H1);
                    t0.y += dot16(ha, hb, hc, hd, wb + 1 * H1);
                    t0.z += dot16(ha, hb, hc, hd, wb + 2 * H1);
                    t0.w += dot16(ha, hb, hc, hd, wb + 3 * H1);
                    t1.x += dot16(ha, hb, hc, hd, wb + 4 * H1);
                    t1.y += dot16(ha, hb, hc, hd, wb + 5 * H1);
                    t1.z += dot16(ha, hb, hc, hd, wb + 6 * H1);
                    t1.w += dot16(ha, hb, hc, hd, wb + 7 * H1);
                    t2.x += dot16(ha, hb, hc, hd, wb + 8 * H1);
                    t2.y += dot16(ha, hb, hc, hd, wb + 9 * H1);
                    t2.z += dot16(ha, hb, hc, hd, wb + 10 * H1);
                    t2.w += dot16(ha, hb, hc, hd, wb + 11 * H1);
                    t3.x += dot16(ha, hb, hc, hd, wb + 12 * H1);
                    t3.y += dot16(ha, hb, hc, hd, wb + 13 * H1);
                    t3.z += dot16(ha, hb, hc, hd, wb + 14 * H1);
                    t3.w += dot16(ha, hb, hc, hd, wb + 15 * H1);
                    t4.x += dot16(ha, hb, hc, hd, wb + 16 * H1);
                    t4.y += dot16(ha, hb, hc, hd, wb + 17 * H1);
                    t4.z += dot16(ha, hb, hc, hd, wb + 18 * H1);
                    t4.w += dot16(ha, hb, hc, hd, wb + 19 * H1);
                    t5.x += dot16(ha, hb, hc, hd, wb + 20 * H1);
                    t5.y += dot16(ha, hb, hc, hd, wb + 21 * H1);
                    t5.z += dot16(ha, hb, hc, hd, wb + 22 * H1);
                    t5.w += dot16(ha, hb, hc, hd, wb + 23 * H1);
                    t6.x += dot16(ha, hb, hc, hd, wb + 24 * H1);
                    t6.y += dot16(ha, hb, hc, hd, wb + 25 * H1);
                    t6.z += dot16(ha, hb, hc, hd, wb + 26 * H1);
                    t6.w += dot16(ha, hb, hc, hd, wb + 27 * H1);
                    t7.x += dot16(ha, hb, hc, hd, wb + 28 * H1);
                    t7.y += dot16(ha, hb, hc, hd, wb + 29 * H1);
                    t7.z += dot16(ha, hb, hc, hd, wb + 30 * H1);
                    t7.w += dot16(ha, hb, hc, hd, wb + 31 * H1);
                }
#define EP(TP, ACC) { ACC.x += fmaxf(TP.x, 0.f); ACC.y += fmaxf(TP.y, 0.f);    \
                      ACC.z += fmaxf(TP.z, 0.f); ACC.w += fmaxf(TP.w, 0.f); }
                EP(t0, c0) EP(t1, c1) EP(t2, c2) EP(t3, c3)
                EP(t4, c4) EP(t5, c5) EP(t6, c6) EP(t7, c7)
#undef EP
            }
        }
        R(c0, 0) R(c1, 1) R(c2, 2) R(c3, 3) R(c4, 4) R(c5, 5) R(c6, 6) R(c7, 7)
#undef R
        __syncthreads();
        if (tid < H2) {
            float v = 0.f;
            for (int w = 0; w < nw; w++) v += s_part[w][tid];
            g_h2p1[blockIdx.x * H2 + tid] = v;
        }
        __syncthreads();
    }

    // ================= phase C: entropy (needs mst partials) =================
    {
        float s0 = 0.f, s1 = 0.f;
        for (int i = tid; i < nblkm; i += blockDim.x) { s0 += g_sp0[i]; s1 += g_sp1[i]; }
        s0 = warp_red(s0); s1 = warp_red(s1);
        if (lane == 0) { s_bc[0][wid] = s0; s_bc[1][wid] = s1; }
        __syncthreads();
        float S0 = 0.f, S1 = 0.f;
        for (int w = 0; w < nw; w++) { S0 += s_bc[0][w]; S1 += s_bc[1][w]; }
        S0 = fmaxf(S0, 1e-30f); S1 = fmaxf(S1, 1e-30f);
        float e = 0.f;
        for (int bb = gbase; bb < B; bb += stride) {
            float p = g_p0[bb];
            if (p > 0.f)  { float q = p  / S0; e -= q * logf(q + 1e-10f); }
            float pb = g_p1b[bb];
            if (pb > 0.f) { float q = pb / S1; e -= q * logf(q + 1e-10f); }
            float pd = g_p1d[bb];
            if (pd > 0.f) { float q = pd / S1; e -= q * logf(q + 1e-10f); }
        }
        e = warp_red(e);
        if (lane == 0) s_part[wid][0] = e;
        __syncthreads();
        if (tid == 0) {
            float v = 0.f;
            for (int w = 0; w < nw; w++) v += s_part[w][0];
            g_epart[blockIdx.x] = v;
        }
    }

    // ================= last block: features + entropy write =================
    __threadfence();
    if (tid == 0) s_last = (atomicAdd(&g_done, 1) == (int)gridDim.x - 1) ? 1 : 0;
    __syncthreads();
    if (s_last) {
        __shared__ float u[H2];
        // parallel reduction of DIAGG x H2 partials, staged in dead sA region
        float* rbuf = (float*)sA;                   // 512 floats (sA is dead now)
        {
            int k = tid & 31, chunk = tid >> 5;     // 8 chunks x 32 k
            float v0 = 0.f, v1 = 0.f;
            for (int blk = chunk; blk < DIAGG; blk += 8) {
                v0 += g_h2p0[blk * H2 + k];
                v1 += g_h2p1[blk * H2 + k];
            }
            rbuf[chunk * H2 + k] = v0;
            rbuf[256 + chunk * H2 + k] = v1;
        }
        __syncthreads();
        if (tid < H2) {
            float v0 = 0.f, v1 = 0.f;
#pragma unroll
            for (int c = 0; c < 8; c++) {
                v0 += rbuf[c * H2 + tid];
                v1 += rbuf[256 + c * H2 + tid];
            }
            u[tid] = v0 / ((float)NEDGE * (float)B) + v1 / ((float)NF1 * (float)B);
        }
        __syncthreads();
        for (int f = tid; f < FDIM; f += blockDim.x) {
            float t = 2.f * b3[f];
#pragma unroll
            for (int k = 0; k < H2; k++) t += u[k] * W3[k * FDIM + f];
            out[f] = t;
        }
        {
            float v = 0.f;
            for (int i = tid; i < DIAGG; i += blockDim.x) v += g_epart[i];
            v = warp_red(v);
            if (lane == 0) s_part[wid][1] = v;
            __syncthreads();
            if (tid == 0) {
                float tot = 0.f;
                for (int w = 0; w < nw; w++) tot += s_part[w][1];
                *ent = tot;
                g_done = 0;   // reset for next graph replay
            }
        }
    }
}

// ---------------- launch ----------------
extern "C" void kernel_launch(void* const* d_in, const int* in_sizes, int n_in,
                              void* d_out, int out_size) {
    const float* pc = (const float*)d_in[0];
    const float* rb = (const float*)d_in[1];
    const float* rd = (const float*)d_in[2];
    const float* W1 = (const float*)d_in[3];
    const float* b1 = (const float*)d_in[4];
    const float* W2 = (const float*)d_in[5];
    const float* b2 = (const float*)d_in[6];
    const float* W3 = (const float*)d_in[7];
    const float* b3 = (const float*)d_in[8];
    float* out = (float*)d_out;

    int B = in_sizes[1] / NF1;
    if (B > BMAX) B = BMAX;
    int nblkm = (B + 127) / 128;

    float* euler = out + FDIM;
    float* ent   = out + FDIM + B;

    k_mst<<<nblkm + NTBLK, 128>>>(pc, rb, rd, W1, b1, W2, b2, euler, B);
    k_diag<<<DIAGG, 256>>>(W1, b1, W2, b2, rb, rd, W3, b3, out, ent, B, nblkm);
}

// round 17
// speedup vs baseline: 1.4598x; 1.1206x over previous
#include <cuda_runtime.h>
#include <math.h>

#define NPTS  14
#define NEDGE 13
#define NF1   3
#define BMAX  65536
#define FDIM  512
#define H1    64
#define H2    32
#define NSEG  (H1 + 1)
#define SROW4 9            // 9 float4 = 36 floats padded row
#define BIGF  1e30f
#define DIAGG 444          // diag grid (3 blocks/SM, one wave)
#define MSTB  520          // max mst blocks
#define NTBLK 16           // table-builder blocks

// ---------------- scratch (all write-once per launch; no zero-init needed) --------
__device__ float  g_deaths0[NEDGE * BMAX];
__device__ float  g_dmax[BMAX];
__device__ float  g_p0[BMAX];
__device__ float  g_p1b[BMAX];
__device__ float  g_p1d[BMAX];
__device__ float  g_sp0[MSTB];
__device__ float  g_sp1[MSTB];
__device__ float  g_h2p0[DIAGG * H2];
__device__ float  g_h2p1[DIAGG * H2];
__device__ float  g_epart[DIAGG];
__device__ float  g_bp0[H1];
__device__ float  g_bp1[H1];
__device__ float4 g_A4[NSEG * SROW4];
__device__ float4 g_C4[NSEG * SROW4];
__device__ float4 g_P4[NSEG * SROW4];
__device__ float4 g_Q4[NSEG * SROW4];
__device__ int    g_fast;
__device__ int    g_done = 0;

__device__ __forceinline__ float warp_red(float v) {
#pragma unroll
    for (int o = 16; o; o >>= 1) v += __shfl_xor_sync(0xffffffffu, v, o);
    return v;
}

// 16-wide dot (fallback path)
__device__ __forceinline__ float dot16(float4 ha, float4 hb, float4 hc, float4 hd,
                                       const float* base) {
    const float4* wv = (const float4*)base;
    float4 w0 = wv[0], w1 = wv[1], w2 = wv[2], w3 = wv[3];
    float s;
    s = ha.x * w0.x;
    s = fmaf(ha.y, w0.y, s); s = fmaf(ha.z, w0.z, s); s = fmaf(ha.w, w0.w, s);
    s = fmaf(hb.x, w1.x, s); s = fmaf(hb.y, w1.y, s); s = fmaf(hb.z, w1.z, s); s = fmaf(hb.w, w1.w, s);
    s = fmaf(hc.x, w2.x, s); s = fmaf(hc.y, w2.y, s); s = fmaf(hc.z, w2.z, s); s = fmaf(hc.w, w2.w, s);
    s = fmaf(hd.x, w3.x, s); s = fmaf(hd.y, w3.y, s); s = fmaf(hd.z, w3.z, s); s = fmaf(hd.w, w3.w, s);
    return s;
}

// ---------------- k_mst: MST blocks (direct loads) + NTBLK table builders --------
__global__ void __launch_bounds__(128)
k_mst(const float* __restrict__ pc, const float* __restrict__ rb,
      const float* __restrict__ rd,
      const float* __restrict__ W1, const float* __restrict__ b1,
      const float* __restrict__ W2, const float* __restrict__ b2,
      float* __restrict__ euler, int B) {
    int nblkm = gridDim.x - NTBLK;
    int tid = threadIdx.x;
    const float INF = __int_as_float(0x7f800000);

    if ((int)blockIdx.x >= nblkm) {
        // ======== table-builder blocks: weights staged in shared ========
        int rel = blockIdx.x - nblkm;            // 0..NTBLK-1
        __shared__ float sW1[2 * H1], sb1s[H1], sW2s[H1 * H2], sb2s[H2];
        __shared__ float sb0[H1], sb1b[H1], st[H1];
        __shared__ int s_nz;
        if (tid == 0) s_nz = 0;
        for (int i = tid; i < 2 * H1; i += blockDim.x) sW1[i] = W1[i];
        for (int i = tid; i < H1; i += blockDim.x) sb1s[i] = b1[i];
        for (int i = tid; i < H1 * H2; i += blockDim.x) sW2s[i] = W2[i];
        for (int i = tid; i < H2; i += blockDim.x) sb2s[i] = b2[i];
        __syncthreads();
        if (tid < H1) {
            float w = sW1[H1 + tid];
            st[tid] = (w != 0.f) ? (-sb1s[tid] / w) : INF;
            if (sb1s[tid] != 0.f) atomicAdd(&s_nz, 1);
        }
        __syncthreads();
        if (tid < H1) {
            float t = st[tid];
            int r = 0;
#pragma unroll
            for (int i = 0; i < H1; i++) {
                float ti = st[i];
                r += (ti < t || (ti == t && i < tid)) ? 1 : 0;
            }
            sb0[r] = t;
            if (rel == 0) g_bp0[r] = t;
        }
        __syncthreads();
        if (tid < H1) {
            float w0 = sW1[tid], w1 = sW1[H1 + tid];
            st[tid] = (w0 != 0.f) ? (-w1 / w0) : INF;
        }
        __syncthreads();
        if (tid < H1) {
            float t = st[tid];
            int r = 0;
#pragma unroll
            for (int i = 0; i < H1; i++) {
                float ti = st[i];
                r += (ti < t || (ti == t && i < tid)) ? 1 : 0;
            }
            sb1b[r] = t;
            if (rel == 0) g_bp1[r] = t;
        }
        if (rel == 0 && tid == 0) g_fast = (s_nz == 0) ? 1 : 0;
        __syncthreads();
        int gt = rel * 128 + tid;
        for (int e = gt; e < NSEG * H2; e += NTBLK * 128) {
            int s = e >> 5, k = e & 31;
            {   // diag0 tables (segment in d)
                float lo = (s == 0)  ? -INF : sb0[s - 1];
                float hi = (s == H1) ?  INF : sb0[s];
                float rep;
                bool li = isinf(lo), hiinf = isinf(hi);
                if (li && hiinf)      rep = 0.f;
                else if (li)          rep = hi - 1.f;
                else if (hiinf)       rep = lo + 1.f;
                else                  rep = 0.5f * (lo + hi);
                float A = 0.f, C = sb2s[k];
#pragma unroll 1
                for (int j = 0; j < H1; j++) {
                    float w = sW1[H1 + j], bb = sb1s[j];
                    bool act = (w == 0.f) ? (bb > 0.f) : ((w * rep + bb) > 0.f);
                    if (act) {
                        float m = sW2s[j * H2 + k];
                        A += w * m;
                        C += bb * m;
                    }
                }
                ((float*)g_A4)[s * (SROW4 * 4) + k] = A;
                ((float*)g_C4)[s * (SROW4 * 4) + k] = C;
            }
            {   // diag1 tables (segment in t = x/y)
                float lo = (s == 0)  ? -INF : sb1b[s - 1];
                float hi = (s == H1) ?  INF : sb1b[s];
                float rep;
                bool li = isinf(lo), hiinf = isinf(hi);
                if (li && hiinf)      rep = 0.f;
                else if (li)          rep = hi - 1.f;
                else if (hiinf)       rep = lo + 1.f;
                else                  rep = 0.5f * (lo + hi);
                float P = 0.f, Q = 0.f;
#pragma unroll 1
                for (int j = 0; j < H1; j++) {
                    float w0 = sW1[j], w1 = sW1[H1 + j];
                    bool act = (w0 == 0.f) ? (w1 > 0.f) : ((w0 * rep + w1) > 0.f);
                    if (act) {
                        float m = sW2s[j * H2 + k];
                        P += w0 * m;
                        Q += w1 * m;
                    }
                }
                ((float*)g_P4)[s * (SROW4 * 4) + k] = P;
                ((float*)g_Q4)[s * (SROW4 * 4) + k] = Q;
            }
        }
        return;
    }

    // ======== MST blocks (direct global loads, no staging) ========
    int b = blockIdx.x * blockDim.x + tid;
    float s0 = 0.f, s1 = 0.f;
    if (b < B) {
        const float* p = pc + (long long)b * (NPTS * 3);
        float px[NPTS], py[NPTS], pz[NPTS];
#pragma unroll
        for (int i = 0; i < NPTS; i++) {
            px[i] = p[3 * i]; py[i] = p[3 * i + 1]; pz[i] = p[3 * i + 2];
        }
        float key[NPTS];
        float dmax2 = 0.f;
        key[0] = BIGF;
#pragma unroll
        for (int i = 1; i < NPTS; i++) {
            float dx = px[i] - px[0], dy = py[i] - py[0], dz = pz[i] - pz[0];
            float d2 = dx * dx + dy * dy + dz * dz;
            key[i] = d2;
            dmax2 = fmaxf(dmax2, d2);
        }
        float m1 = BIGF, m2 = BIGF;
#pragma unroll 1
        for (int it = 0; it < NEDGE; it++) {
#define MINP(AV, AI, BV, BI, OV, OI) \
            { bool c = (BV) < (AV); OV = c ? (BV) : (AV); OI = c ? (BI) : (AI); }
            float v12, v34, v56, v78, v910, v1112;
            int   i12, i34, i56, i78, i910, i1112;
            MINP(key[1], 1, key[2], 2, v12, i12)
            MINP(key[3], 3, key[4], 4, v34, i34)
            MINP(key[5], 5, key[6], 6, v56, i56)
            MINP(key[7], 7, key[8], 8, v78, i78)
            MINP(key[9], 9, key[10], 10, v910, i910)
            MINP(key[11], 11, key[12], 12, v1112, i1112)
            float va, vb, vc; int ia, ib, ic;
            MINP(v12, i12, v34, i34, va, ia)
            MINP(v56, i56, v78, i78, vb, ib)
            MINP(v910, i910, v1112, i1112, vc, ic)
            float vab; int iab;
            MINP(va, ia, vb, ib, vab, iab)
            float vcd; int icd;
            MINP(vc, ic, key[13], 13, vcd, icd)
            float bv; int bj;
            MINP(vab, iab, vcd, icd, bv, bj)
#undef MINP
            if (bv < m1) { m2 = m1; m1 = bv; } else if (bv < m2) { m2 = bv; }
            g_deaths0[it * B + b] = sqrtf(fmaxf(bv, 1e-24f));
            float qx = px[0], qy = py[0], qz = pz[0];
#pragma unroll
            for (int c = 1; c < NPTS; c++) {
                if (bj == c) { qx = px[c]; qy = py[c]; qz = pz[c]; }
            }
#pragma unroll
            for (int i = 1; i < NPTS; i++) {
                float dx = px[i] - qx, dy = py[i] - qy, dz = pz[i] - qz;
                float d2 = dx * dx + dy * dy + dz * dz;
                dmax2 = fmaxf(dmax2, d2);
                float nk = fminf(key[i], d2);
                key[i] = (i == bj || key[i] >= BIGF) ? BIGF : nk;
            }
        }
        float dmax = sqrtf(fmaxf(dmax2, 1e-24f));
        g_dmax[b] = dmax;
        float d0 = sqrtf(fmaxf(m1, 1e-24f));
        float d1 = sqrtf(fmaxf(m2, 1e-24f));
        float p0 = d1 - d0;
        g_p0[b] = p0;
        if (p0 > 0.f) s0 = p0;
        float p1b = (rb[b * NF1 + 1] - rb[b * NF1 + 0]) * dmax * 0.3f;
        float p1d = p1b + (rd[b * NF1 + 1] - rd[b * NF1 + 0]) * dmax * 0.4f;
        g_p1b[b] = p1b;
        g_p1d[b] = p1d;
        if (p1b > 0.f) s1 += p1b;
        if (p1d > 0.f) s1 += p1d;
        euler[b] = (float)(NEDGE - NF1);
    }
    __shared__ float s_e[2][4];
    int lane = tid & 31, wid = tid >> 5;
    int nw = blockDim.x >> 5;
    s0 = warp_red(s0);
    s1 = warp_red(s1);
    if (lane == 0) { s_e[0][wid] = s0; s_e[1][wid] = s1; }
    __syncthreads();
    if (wid == 0 && lane < 2) {
        float v = 0.f;
        for (int w = 0; w < nw; w++) v += s_e[lane][w];
        if (lane == 0) g_sp0[blockIdx.x] = v; else g_sp1[blockIdx.x] = v;
    }
}

// ---------------- k_diag: diag0 + diag1 + entropy + (last block) features --------
// Register-dieted (<=84 target) for 3 blocks/SM. Phase A k-chunked; phase B reads
// biases from shared. Fallback paths chunked too (no spills).
__global__ void __launch_bounds__(256, 3)
k_diag(const float* __restrict__ W1, const float* __restrict__ b1,
       const float* __restrict__ W2, const float* __restrict__ b2,
       const float* __restrict__ rb, const float* __restrict__ rd,
       const float* __restrict__ W3, const float* __restrict__ b3,
       float* __restrict__ out, float* __restrict__ ent, int B, int nblkm) {
    __shared__ float  sbp0[H1], sbp1[H1];
    __shared__ __align__(16) float4 sA[NSEG * SROW4];
    __shared__ __align__(16) float4 sC[NSEG * SROW4];
    __shared__ __align__(16) float4 sP[NSEG * SROW4];   // fast: t-tables | fallback: sw + sW2t
    __shared__ __align__(16) float4 sQ[NSEG * SROW4];
    __shared__ __align__(16) float4 sb2v[8];
    __shared__ float s_part[8][H2];
    __shared__ float s_bc[2][8];
    __shared__ int s_last;
    float* sw   = (float*)sP;                 // fallback: H1*4 floats
    float* sW2t = (float*)sQ;                 // fallback: H2*H1 floats
    int tid = threadIdx.x;
    int fast = g_fast;
    for (int i = tid; i < H1; i += blockDim.x) { sbp0[i] = g_bp0[i]; sbp1[i] = g_bp1[i]; }
    for (int i = tid; i < NSEG * SROW4; i += blockDim.x) {
        sA[i] = g_A4[i]; sC[i] = g_C4[i];
    }
    if (fast) {
        for (int i = tid; i < NSEG * SROW4; i += blockDim.x) {
            sP[i] = g_P4[i]; sQ[i] = g_Q4[i];
        }
    } else {
        for (int j = tid; j < H1; j += blockDim.x) {
            sw[j * 4 + 0] = W1[j];
            sw[j * 4 + 1] = W1[H1 + j];
            sw[j * 4 + 2] = b1[j];
            sw[j * 4 + 3] = 0.f;
        }
        for (int i = tid; i < H1 * H2; i += blockDim.x) {
            int j = i / H2, k = i % H2;
            sW2t[k * H1 + j] = W2[i];
        }
    }
    if (tid < 8) sb2v[tid] = ((const float4*)b2)[tid];
    __syncthreads();

    int lane = tid & 31, wid = tid >> 5;
    int nw = blockDim.x >> 5;
    int stride = gridDim.x * blockDim.x;
    int gbase = blockIdx.x * blockDim.x + tid;
    float4 z = make_float4(0.f, 0.f, 0.f, 0.f);

#define R(ACC, q) {                                                        \
    float vx = warp_red(ACC.x), vy = warp_red(ACC.y);                      \
    float vz = warp_red(ACC.z), vw = warp_red(ACC.w);                      \
    if (lane == 0) { s_part[wid][(q) * 4 + 0] = vx; s_part[wid][(q) * 4 + 1] = vy; \
                     s_part[wid][(q) * 4 + 2] = vz; s_part[wid][(q) * 4 + 3] = vw; } }

    // ================= phase A: diag0 over MST deaths (k-chunked) =================
    {
        int total = NEDGE * B;
        int total4 = total >> 2;
        int loA = 0;
        if (fast) {
            int lo = 0, hi = H1;
#pragma unroll
            for (int s = 0; s < 6; s++) {
                int mid = (lo + hi) >> 1;
                if (sbp0[mid] < 1e-20f) lo = mid + 1; else hi = mid;
            }
            loA = lo;
        }
#pragma unroll 1
        for (int kc = 0; kc < 2; kc++) {
            float4 a0 = z, a1 = z, a2 = z, a3 = z;
            if (fast) {
                const float4* Av = sA + loA * SROW4 + kc * 4;
                const float4* Cv = sC + loA * SROW4 + kc * 4;
                float4 A0 = Av[0], A1 = Av[1], A2 = Av[2], A3 = Av[3];
                float4 C0 = Cv[0], C1 = Cv[1], C2 = Cv[2], C3 = Cv[3];
                const float4* dp = (const float4*)g_deaths0;
#define Q0(ACC, AV, CV, D) {                                              \
                ACC.x += fmaxf(fmaf(AV.x, D, CV.x), 0.f);                 \
                ACC.y += fmaxf(fmaf(AV.y, D, CV.y), 0.f);                 \
                ACC.z += fmaxf(fmaf(AV.z, D, CV.z), 0.f);                 \
                ACC.w += fmaxf(fmaf(AV.w, D, CV.w), 0.f); }
#define QALL(D) { Q0(a0, A0, C0, D) Q0(a1, A1, C1, D)                     \
                  Q0(a2, A2, C2, D) Q0(a3, A3, C3, D) }
                for (int i4 = gbase; i4 < total4; i4 += stride) {
                    float4 d4 = dp[i4];
                    QALL(d4.x) QALL(d4.y) QALL(d4.z) QALL(d4.w)
                }
                for (int i = (total4 << 2) + gbase; i < total; i += stride) {
                    float d = g_deaths0[i];
                    QALL(d)
                }
#undef QALL
#undef Q0
            } else {
                for (int i = gbase; i < total; i += stride) {
                    float d = g_deaths0[i];
                    int lo = 0, hi = H1;
#pragma unroll
                    for (int s = 0; s < 6; s++) {
                        int mid = (lo + hi) >> 1;
                        if (sbp0[mid] < d) lo = mid + 1; else hi = mid;
                    }
                    const float4* Av = sA + lo * SROW4 + kc * 4;
                    const float4* Cv = sC + lo * SROW4 + kc * 4;
#define Q1(ACC, q) { float4 A = Av[q], C = Cv[q];                         \
                    ACC.x += fmaxf(fmaf(A.x, d, C.x), 0.f);               \
                    ACC.y += fmaxf(fmaf(A.y, d, C.y), 0.f);               \
                    ACC.z += fmaxf(fmaf(A.z, d, C.z), 0.f);               \
                    ACC.w += fmaxf(fmaf(A.w, d, C.w), 0.f); }
                    Q1(a0, 0) Q1(a1, 1) Q1(a2, 2) Q1(a3, 3)
#undef Q1
                }
            }
            R(a0, kc * 4 + 0) R(a1, kc * 4 + 1) R(a2, kc * 4 + 2) R(a3, kc * 4 + 3)
        }
        __syncthreads();
        if (tid < H2) {
            float v = 0.f;
            for (int w = 0; w < nw; w++) v += s_part[w][tid];
            g_h2p0[blockIdx.x * H2 + tid] = v;
        }
        __syncthreads();
    }

    // ================= phase B: diag1 over random features =================
    {
        int total = NF1 * B;
        if (fast) {
            float4 c0 = z, c1 = z, c2 = z, c3 = z, c4 = z, c5 = z, c6 = z, c7 = z;
            for (int i = gbase; i < total; i += stride) {
                float dm = g_dmax[i / NF1];
                float x = rb[i] * dm * 0.3f;
                float y = fmaf(rd[i] * dm, 0.4f, x);
                float t = (y > 0.f) ? (x / y) : 0.f;
                int lo = 0, hi = H1;
#pragma unroll
                for (int s = 0; s < 6; s++) {
                    int mid = (lo + hi) >> 1;
                    if (sbp1[mid] < t) lo = mid + 1; else hi = mid;
                }
                const float4* Pv = sP + lo * SROW4;
                const float4* Qv = sQ + lo * SROW4;
#define Q2(ACC, q) { float4 P = Pv[q], Q = Qv[q], BV = sb2v[q];            \
                ACC.x += fmaxf(fmaf(y, fmaf(P.x, t, Q.x), BV.x), 0.f);     \
                ACC.y += fmaxf(fmaf(y, fmaf(P.y, t, Q.y), BV.y), 0.f);     \
                ACC.z += fmaxf(fmaf(y, fmaf(P.z, t, Q.z), BV.z), 0.f);     \
                ACC.w += fmaxf(fmaf(y, fmaf(P.w, t, Q.w), BV.w), 0.f); }
                Q2(c0, 0) Q2(c1, 1) Q2(c2, 2) Q2(c3, 3)
                Q2(c4, 4) Q2(c5, 5) Q2(c6, 6) Q2(c7, 7)
#undef Q2
            }
            R(c0, 0) R(c1, 1) R(c2, 2) R(c3, 3) R(c4, 4) R(c5, 5) R(c6, 6) R(c7, 7)
        } else {
            // exact per-point MLP, k-chunked (16 outputs per pass)
#pragma unroll 1
            for (int kc = 0; kc < 2; kc++) {
                float4 c0 = z, c1 = z, c2 = z, c3 = z;
                for (int i = gbase; i < total; i += stride) {
                    float dm = g_dmax[i / NF1];
                    float x = rb[i] * dm * 0.3f;
                    float y = fmaf(rd[i] * dm, 0.4f, x);
                    float4 t0 = sb2v[kc * 4 + 0], t1 = sb2v[kc * 4 + 1];
                    float4 t2 = sb2v[kc * 4 + 2], t3 = sb2v[kc * 4 + 3];
#pragma unroll 1
                    for (int jc = 0; jc < 4; jc++) {
                        const float4* swv = (const float4*)sw + jc * 16;
                        float4 ha, hb, hc, hd;
#define HV(DST, COMP, IDX) { float4 w = swv[IDX];                              \
                        DST.COMP = fmaxf(fmaf(x, w.x, fmaf(y, w.y, w.z)), 0.f); }
                        HV(ha, x, 0)  HV(ha, y, 1)  HV(ha, z, 2)  HV(ha, w, 3)
                        HV(hb, x, 4)  HV(hb, y, 5)  HV(hb, z, 6)  HV(hb, w, 7)
                        HV(hc, x, 8)  HV(hc, y, 9)  HV(hc, z, 10) HV(hc, w, 11)
                        HV(hd, x, 12) HV(hd, y, 13) HV(hd, z, 14) HV(hd, w, 15)
#undef HV
                        const float* wb = sW2t + (kc * 16) * H1 + jc * 16;
                        t0.x += dot16(ha, hb, hc, hd, wb + 0 * H1);
                        t0.y += dot16(ha, hb, hc, hd, wb + 1 * H1);
                        t0.z += dot16(ha, hb, hc, hd, wb + 2 * H1);
                        t0.w += dot16(ha, hb, hc, hd, wb + 3 * H1);
                        t1.x += dot16(ha, hb, hc, hd, wb + 4 * H1);
                        t1.y += dot16(ha, hb, hc, hd, wb + 5 * H1);
                        t1.z += dot16(ha, hb, hc, hd, wb + 6 * H1);
                        t1.w += dot16(ha, hb, hc, hd, wb + 7 * H1);
                        t2.x += dot16(ha, hb, hc, hd, wb + 8 * H1);
                        t2.y += dot16(ha, hb, hc, hd, wb + 9 * H1);
                        t2.z += dot16(ha, hb, hc, hd, wb + 10 * H1);
                        t2.w += dot16(ha, hb, hc, hd, wb + 11 * H1);
                        t3.x += dot16(ha, hb, hc, hd, wb + 12 * H1);
                        t3.y += dot16(ha, hb, hc, hd, wb + 13 * H1);
                        t3.z += dot16(ha, hb, hc, hd, wb + 14 * H1);
                        t3.w += dot16(ha, hb, hc, hd, wb + 15 * H1);
                    }
                    c0.x += fmaxf(t0.x, 0.f); c0.y += fmaxf(t0.y, 0.f);
                    c0.z += fmaxf(t0.z, 0.f); c0.w += fmaxf(t0.w, 0.f);
                    c1.x += fmaxf(t1.x, 0.f); c1.y += fmaxf(t1.y, 0.f);
                    c1.z += fmaxf(t1.z, 0.f); c1.w += fmaxf(t1.w, 0.f);
                    c2.x += fmaxf(t2.x, 0.f); c2.y += fmaxf(t2.y, 0.f);
                    c2.z += fmaxf(t2.z, 0.f); c2.w += fmaxf(t2.w, 0.f);
                    c3.x += fmaxf(t3.x, 0.f); c3.y += fmaxf(t3.y, 0.f);
                    c3.z += fmaxf(t3.z, 0.f); c3.w += fmaxf(t3.w, 0.f);
                }
                R(c0, kc * 4 + 0) R(c1, kc * 4 + 1) R(c2, kc * 4 + 2) R(c3, kc * 4 + 3)
            }
        }
        __syncthreads();
        if (tid < H2) {
            float v = 0.f;
            for (int w = 0; w < nw; w++) v += s_part[w][tid];
            g_h2p1[blockIdx.x * H2 + tid] = v;
        }
        __syncthreads();
    }
#undef R

    // ================= phase C: entropy (needs mst partials) =================
    {
        float s0 = 0.f, s1 = 0.f;
        for (int i = tid; i < nblkm; i += blockDim.x) { s0 += g_sp0[i]; s1 += g_sp1[i]; }
        s0 = warp_red(s0); s1 = warp_red(s1);
        if (lane == 0) { s_bc[0][wid] = s0; s_bc[1][wid] = s1; }
        __syncthreads();
        float S0 = 0.f, S1 = 0.f;
        for (int w = 0; w < nw; w++) { S0 += s_bc[0][w]; S1 += s_bc[1][w]; }
        S0 = fmaxf(S0, 1e-30f); S1 = fmaxf(S1, 1e-30f);
        float e = 0.f;
        for (int bb = gbase; bb < B; bb += stride) {
            float p = g_p0[bb];
            if (p > 0.f)  { float q = p  / S0; e -= q * logf(q + 1e-10f); }
            float pb = g_p1b[bb];
            if (pb > 0.f) { float q = pb / S1; e -= q * logf(q + 1e-10f); }
            float pd = g_p1d[bb];
            if (pd > 0.f) { float q = pd / S1; e -= q * logf(q + 1e-10f); }
        }
        e = warp_red(e);
        if (lane == 0) s_part[wid][0] = e;
        __syncthreads();
        if (tid == 0) {
            float v = 0.f;
            for (int w = 0; w < nw; w++) v += s_part[w][0];
            g_epart[blockIdx.x] = v;
        }
    }

    // ================= last block: features + entropy write =================
    __threadfence();
    if (tid == 0) s_last = (atomicAdd(&g_done, 1) == (int)gridDim.x - 1) ? 1 : 0;
    __syncthreads();
    if (s_last) {
        __shared__ float u[H2];
        float* rbuf = (float*)sA;                   // 512 floats (sA is dead now)
        {
            int k = tid & 31, chunk = tid >> 5;     // 8 chunks x 32 k
            float v0 = 0.f, v1 = 0.f;
            for (int blk = chunk; blk < DIAGG; blk += 8) {
                v0 += g_h2p0[blk * H2 + k];
                v1 += g_h2p1[blk * H2 + k];
            }
            rbuf[chunk * H2 + k] = v0;
            rbuf[256 + chunk * H2 + k] = v1;
        }
        __syncthreads();
        if (tid < H2) {
            float v0 = 0.f, v1 = 0.f;
#pragma unroll
            for (int c = 0; c < 8; c++) {
                v0 += rbuf[c * H2 + tid];
                v1 += rbuf[256 + c * H2 + tid];
            }
            u[tid] = v0 / ((float)NEDGE * (float)B) + v1 / ((float)NF1 * (float)B);
        }
        __syncthreads();
        for (int f = tid; f < FDIM; f += blockDim.x) {
            float t = 2.f * b3[f];
#pragma unroll
            for (int k = 0; k < H2; k++) t += u[k] * W3[k * FDIM + f];
            out[f] = t;
        }
        {
            float v = 0.f;
            for (int i = tid; i < DIAGG; i += blockDim.x) v += g_epart[i];
            v = warp_red(v);
            if (lane == 0) s_part[wid][1] = v;
            __syncthreads();
            if (tid == 0) {
                float tot = 0.f;
                for (int w = 0; w < nw; w++) tot += s_part[w][1];
                *ent = tot;
                g_done = 0;   // reset for next graph replay
            }
        }
    }
}

// ---------------- launch ----------------
extern "C" void kernel_launch(void* const* d_in, const int* in_sizes, int n_in,
                              void* d_out, int out_size) {
    const float* pc = (const float*)d_in[0];
    const float* rb = (const float*)d_in[1];
    const float* rd = (const float*)d_in[2];
    const float* W1 = (const float*)d_in[3];
    const float* b1 = (const float*)d_in[4];
    const float* W2 = (const float*)d_in[5];
    const float* b2 = (const float*)d_in[6];
    const float* W3 = (const float*)d_in[7];
    const float* b3 = (const float*)d_in[8];
    float* out = (float*)d_out;

    int B = in_sizes[1] / NF1;
    if (B > BMAX) B = BMAX;
    int nblkm = (B + 127) / 128;

    float* euler = out + FDIM;
    float* ent   = out + FDIM + B;

    k_mst<<<nblkm + NTBLK, 128>>>(pc, rb, rd, W1, b1, W2, b2, euler, B);
    k_diag<<<DIAGG, 256>>>(W1, b1, W2, b2, rb, rd, W3, b3, out, ent, B, nblkm);
}